// round 7
// baseline (speedup 1.0000x reference)
#include <cuda_runtime.h>
#include <cuda_fp16.h>
#include <math.h>
#include <stdint.h>

#define BSZ 2
#define SEQ 1024
#define TXT 512
#define DIMM 1536
#define NH 12
#define HDD 128
#define NKV 4
#define JD 3584
#define NE 16
#define NI 1344
#define CAP 512
#define LTOT 1536      // SEQ + TXT
#define NTOK 2048      // BSZ*SEQ
#define MROWS 16384    // NE*BSZ*CAP
#define IKV 512        // NKV*HDD
#define REP 3          // NH/NKV
#define EPSL 1e-6f

// ------------------------- scratch (device globals) -------------------------
__device__ float g_scale1[BSZ*DIMM];
__device__ float g_tg1[BSZ*DIMM];
__device__ float g_scale2[BSZ*DIMM];
__device__ float g_tg2[BSZ*DIMM];
__device__ float g_ctx[BSZ*TXT*DIMM];
__device__ float g_imgmod[NTOK*DIMM];
__device__ float g_q[NTOK*DIMM];
__device__ float g_kimg[NTOK*IKV];
__device__ float g_vimg[NTOK*IKV];
__device__ float g_ktxt[BSZ*TXT*IKV];
__device__ float g_vtxt[BSZ*TXT*IKV];
__device__ float g_k[BSZ*NKV*LTOT*HDD];
__device__ float g_v[BSZ*NKV*LTOT*HDD];
__device__ float g_attn[NTOK*DIMM];
__device__ float g_hs1[NTOK*DIMM];
__device__ float g_normed2[NTOK*DIMM];
__device__ float g_mod2[NTOK*DIMM];
__device__ float g_tembdot[BSZ*NE];
__device__ float g_aff[BSZ*NE*SEQ];
__device__ int   g_topidx[BSZ*NE*CAP];
__device__ float g_gating[BSZ*NE*CAP];
__device__ float g_sums[NTOK];
__device__ int   g_rowmap[MROWS];
__device__ float g_rscale[MROWS];
__device__ float g_hmoe[(size_t)MROWS*2*NI];
__device__ float g_actmoe[(size_t)MROWS*NI];
__device__ float g_hsh[NTOK*2*NI];
__device__ float g_actsh[NTOK*NI];
__device__ float g_outflat[NTOK*DIMM];

// ======================= helpers ============================================
__device__ __forceinline__ uint32_t s2u(const void* p) {
    uint32_t a;
    asm("{ .reg .u64 t; cvta.to.shared.u64 t, %1; cvt.u32.u64 %0, t; }"
        : "=r"(a) : "l"(p));
    return a;
}
__device__ __forceinline__ void ld16(const float* __restrict__ p, float* d) {
    #pragma unroll
    for (int i = 0; i < 4; i++) *(float4*)(d + 4*i) = *(const float4*)(p + 4*i);
}
// 16 fp32 -> hi/lo fp16 split, packed as 2+2 uint4
__device__ __forceinline__ void cvt16(const float* f, uint4* hs, uint4* ls) {
    union { __half h[16]; uint4 u[2]; } H, L;
    #pragma unroll
    for (int i = 0; i < 16; i++) {
        __half hh = __float2half(f[i]);
        H.h[i] = hh;
        L.h[i] = __float2half(f[i] - __half2float(hh));
    }
    hs[0] = H.u[0]; hs[1] = H.u[1];
    ls[0] = L.u[0]; ls[1] = L.u[1];
}
__device__ __forceinline__ void mma16816(float* c, const uint32_t* a, const uint32_t* b) {
    asm volatile(
        "mma.sync.aligned.m16n8k16.row.col.f32.f16.f16.f32 "
        "{%0,%1,%2,%3}, {%4,%5,%6,%7}, {%8,%9}, {%0,%1,%2,%3};"
        : "+f"(c[0]), "+f"(c[1]), "+f"(c[2]), "+f"(c[3])
        : "r"(a[0]), "r"(a[1]), "r"(a[2]), "r"(a[3]), "r"(b[0]), "r"(b[1]));
}

// ======================= split-fp16 mma.sync GEMM ===========================
// C[M,N] = A[M,K] * B[N,K]^T at ~fp32 precision via extended-K f16 split:
//   A_ext = [Ah | Ah | Al],  B_ext = [Bh | Bl | Bh]  => AhBh + AhBl + AlBh
// CTA tile 128x128, source-K chunk 32 (ext 96), 256 thr = 8 warps (2x4),
// warp tile 64x32. Double-buffered SMEM (1 barrier/chunk); 2 CTAs/SM.
// EPI 0: store  1: +bias[n]  2: resid + gate[b][n]*acc  3: atomic scatter
// AG: gather A rows through agather[z*M + m].
#define RSB 208                 // smem row stride bytes (96 halves + pad)
#define ASZ (128*RSB)           // 26624
#define BUFSZ (2*ASZ)           // 53248 (A tile + B tile)
#define MMSM (2*BUFSZ)          // 106496 (double buffered)

template<int EPI, bool AG>
__global__ __launch_bounds__(256, 2) void mma_gemm(
    const float* __restrict__ A, const float* __restrict__ B, float* __restrict__ C,
    int M, int N, int K,
    long long sA, long long sB, long long sC,
    const float* __restrict__ bias,
    const float* __restrict__ resid, const float* __restrict__ gate,
    const int* __restrict__ rowmap, const float* __restrict__ rscale,
    const int* __restrict__ agather)
{
    extern __shared__ char smem[];
    const int tid = threadIdx.x;
    const int wid = tid >> 5, lane = tid & 31;
    const int z = blockIdx.z;
    const int m0 = blockIdx.y * 128, n0 = blockIdx.x * 128;
    if (!AG) A += (long long)z * sA;
    B += (long long)z * sB;

    // ---- loader assignment: thread owns row lr, 16-col half lh ----
    const int lr = tid >> 1;
    const int lh = tid & 1;
    long long arow = AG ? (long long)agather[(long long)z * M + m0 + lr]
                        : (long long)(m0 + lr);
    const float* ag = A + arow * (long long)K + lh * 16;
    const float* bg = B + (long long)(n0 + lr) * K + lh * 16;
    const int ldoff = lr * RSB + lh * 32;

    // ---- warp tile / ldmatrix addresses (buffer 0 base; add BUFSZ for buf1) --
    const int wm = (wid >> 2) * 64;
    const int wn = (wid & 3) * 32;
    const uint32_t sAb = s2u(smem);
    const uint32_t sBb = sAb + ASZ;
    uint32_t a_ld[4], b_ld[2];
    #pragma unroll
    for (int mt = 0; mt < 4; mt++) {
        int r = wm + mt * 16 + (lane & 15);
        a_ld[mt] = sAb + r * RSB + (lane >> 4) * 16;
    }
    #pragma unroll
    for (int np = 0; np < 2; np++) {
        int r = wn + np * 16 + ((lane >> 4) << 3) + (lane & 7);
        b_ld[np] = sBb + r * RSB + ((lane >> 3) & 1) * 16;
    }

    float acc[4][4][4];
    #pragma unroll
    for (int mt = 0; mt < 4; mt++)
        #pragma unroll
        for (int nt = 0; nt < 4; nt++)
            #pragma unroll
            for (int i = 0; i < 4; i++) acc[mt][nt][i] = 0.f;

    const int NC = K >> 5;
    float pfa[16], pfb[16];

    // prime buffer 0 with chunk 0
    ld16(ag, pfa);
    ld16(bg, pfb);
    {
        char* Ap = smem + ldoff;
        char* Bp = smem + ASZ + ldoff;
        uint4 h[2], l[2];
        cvt16(pfa, h, l);
        *(uint4*)(Ap +   0) = h[0]; *(uint4*)(Ap +  16) = h[1];
        *(uint4*)(Ap +  64) = h[0]; *(uint4*)(Ap +  80) = h[1];
        *(uint4*)(Ap + 128) = l[0]; *(uint4*)(Ap + 144) = l[1];
        cvt16(pfb, h, l);
        *(uint4*)(Bp +   0) = h[0]; *(uint4*)(Bp +  16) = h[1];
        *(uint4*)(Bp +  64) = l[0]; *(uint4*)(Bp +  80) = l[1];
        *(uint4*)(Bp + 128) = h[0]; *(uint4*)(Bp + 144) = h[1];
    }
    __syncthreads();

    for (int c = 0; c < NC; c++) {
        const uint32_t boff = (c & 1) * BUFSZ;
        const bool more = (c + 1 < NC);
        if (more) {
            ld16(ag + (c + 1) * 32, pfa);   // issue global loads early
            ld16(bg + (c + 1) * 32, pfb);
        }
        // 6 k16 steps over ext-K = 96 on buffer c&1
        #pragma unroll
        for (int ks = 0; ks < 6; ks++) {
            uint32_t af[4][4];
            #pragma unroll
            for (int mt = 0; mt < 4; mt++)
                asm volatile("ldmatrix.sync.aligned.m8n8.x4.shared.b16 {%0,%1,%2,%3}, [%4];"
                    : "=r"(af[mt][0]), "=r"(af[mt][1]), "=r"(af[mt][2]), "=r"(af[mt][3])
                    : "r"(a_ld[mt] + boff + ks * 32));
            uint32_t bf[4][2];
            #pragma unroll
            for (int np = 0; np < 2; np++)
                asm volatile("ldmatrix.sync.aligned.m8n8.x4.shared.b16 {%0,%1,%2,%3}, [%4];"
                    : "=r"(bf[np*2][0]), "=r"(bf[np*2][1]),
                      "=r"(bf[np*2+1][0]), "=r"(bf[np*2+1][1])
                    : "r"(b_ld[np] + boff + ks * 32));
            #pragma unroll
            for (int mt = 0; mt < 4; mt++)
                #pragma unroll
                for (int nt = 0; nt < 4; nt++)
                    mma16816(acc[mt][nt], af[mt], bf[nt]);
        }
        if (more) {
            const uint32_t ob = (~c & 1) * BUFSZ;
            char* Ap = smem + ob + ldoff;
            char* Bp = smem + ob + ASZ + ldoff;
            uint4 h[2], l[2];
            cvt16(pfa, h, l);
            *(uint4*)(Ap +   0) = h[0]; *(uint4*)(Ap +  16) = h[1];
            *(uint4*)(Ap +  64) = h[0]; *(uint4*)(Ap +  80) = h[1];
            *(uint4*)(Ap + 128) = l[0]; *(uint4*)(Ap + 144) = l[1];
            cvt16(pfb, h, l);
            *(uint4*)(Bp +   0) = h[0]; *(uint4*)(Bp +  16) = h[1];
            *(uint4*)(Bp +  64) = l[0]; *(uint4*)(Bp +  80) = l[1];
            *(uint4*)(Bp + 128) = h[0]; *(uint4*)(Bp + 144) = h[1];
        }
        __syncthreads();
    }

    // ---- epilogue ----
    const int g = lane >> 2;
    const int cp2 = (lane & 3) * 2;
    #pragma unroll
    for (int mt = 0; mt < 4; mt++) {
        #pragma unroll
        for (int hh = 0; hh < 2; hh++) {
            int row = m0 + wm + mt * 16 + g + hh * 8;
            if (EPI == 3) {
                long long gr = (long long)z * M + row;
                int trow = rowmap[gr];
                float s = rscale[gr];
                float* cp = C + (long long)trow * N;
                #pragma unroll
                for (int nt = 0; nt < 4; nt++) {
                    int col = n0 + wn + nt * 8 + cp2;
                    atomicAdd(cp + col,     acc[mt][nt][hh*2]   * s);
                    atomicAdd(cp + col + 1, acc[mt][nt][hh*2+1] * s);
                }
            } else {
                float* Cz = C + (long long)z * sC + (long long)row * N;
                #pragma unroll
                for (int nt = 0; nt < 4; nt++) {
                    int col = n0 + wn + nt * 8 + cp2;
                    float v0 = acc[mt][nt][hh*2], v1 = acc[mt][nt][hh*2+1];
                    if (EPI == 1) { v0 += bias[col]; v1 += bias[col + 1]; }
                    if (EPI == 2) {
                        const float* gp = gate + (row / SEQ) * N + col;
                        const float* rp = resid + (long long)row * N + col;
                        v0 = rp[0] + gp[0] * v0;
                        v1 = rp[1] + gp[1] * v1;
                    }
                    *(float2*)(Cz + col) = make_float2(v0, v1);
                }
            }
        }
    }
}

// ------------------------- modulation: mod = silu(temb) @ W_mod^T + b -------
__global__ __launch_bounds__(256) void mod_kernel(const float* __restrict__ temb,
                                                  const float* __restrict__ Wm,
                                                  const float* __restrict__ bm) {
    int gw = (blockIdx.x * blockDim.x + threadIdx.x) >> 5;
    int lane = threadIdx.x & 31;
    if (gw >= BSZ * 4 * DIMM) return;
    int b = gw / (4 * DIMM);
    int j = gw - b * 4 * DIMM;
    const float* t = temb + b * DIMM;
    const float* w = Wm + (size_t)j * DIMM;
    float acc = 0.f;
    for (int kk = lane; kk < DIMM; kk += 32) {
        float x = t[kk];
        acc += (x / (1.f + __expf(-x))) * w[kk];
    }
    #pragma unroll
    for (int o = 16; o; o >>= 1) acc += __shfl_xor_sync(0xffffffffu, acc, o);
    if (lane == 0) {
        acc += bm[j];
        int q = j / DIMM, c = j - q * DIMM;
        if (q == 0)      g_scale1[b*DIMM + c] = 1.f + acc;
        else if (q == 1) g_tg1[b*DIMM + c]    = tanhf(fminf(fmaxf(acc, -2.f), 2.f));
        else if (q == 2) g_scale2[b*DIMM + c] = 1.f + acc;
        else             g_tg2[b*DIMM + c]    = tanhf(fminf(fmaxf(acc, -2.f), 2.f));
    }
}

// ------------------------- LayerNorm (+ scale, optional normed out) ---------
__global__ __launch_bounds__(256) void ln_mod_kernel(const float* __restrict__ in,
                                                     const float* __restrict__ scale,
                                                     float* __restrict__ outmod,
                                                     float* __restrict__ outnorm) {
    int rowi = blockIdx.x;
    int b = rowi >> 10;
    const float* x = in + (size_t)rowi * DIMM;
    float s = 0.f, sq = 0.f;
    for (int d = threadIdx.x; d < DIMM; d += 256) { float v = x[d]; s += v; sq += v * v; }
    #pragma unroll
    for (int o = 16; o; o >>= 1) {
        s  += __shfl_xor_sync(0xffffffffu, s,  o);
        sq += __shfl_xor_sync(0xffffffffu, sq, o);
    }
    __shared__ float rs[8], rq[8], mv[2];
    int w = threadIdx.x >> 5;
    if ((threadIdx.x & 31) == 0) { rs[w] = s; rq[w] = sq; }
    __syncthreads();
    if (threadIdx.x == 0) {
        float S = 0.f, Q = 0.f;
        for (int i = 0; i < 8; i++) { S += rs[i]; Q += rq[i]; }
        float mean = S / DIMM;
        float var = Q / DIMM - mean * mean;
        mv[0] = mean; mv[1] = rsqrtf(var + EPSL);
    }
    __syncthreads();
    float mean = mv[0], rstd = mv[1];
    const float* sc = scale + (size_t)b * DIMM;
    for (int d = threadIdx.x; d < DIMM; d += 256) {
        float n = (x[d] - mean) * rstd;
        if (outnorm) outnorm[(size_t)rowi * DIMM + d] = n;
        outmod[(size_t)rowi * DIMM + d] = n * sc[d];
    }
}

// ------------------------- per-head RMSNorm of Q ----------------------------
__global__ __launch_bounds__(256) void rms_q_kernel(const float* __restrict__ w) {
    int gw = (blockIdx.x * blockDim.x + threadIdx.x) >> 5;
    if (gw >= NTOK * NH) return;
    int lane = threadIdx.x & 31;
    float* p = g_q + (size_t)gw * HDD;
    int d4 = lane << 2;
    float4 v = *(float4*)(p + d4);
    float ss = v.x*v.x + v.y*v.y + v.z*v.z + v.w*v.w;
    #pragma unroll
    for (int o = 16; o; o >>= 1) ss += __shfl_xor_sync(0xffffffffu, ss, o);
    float r = rsqrtf(ss / HDD + EPSL);
    float4 wv = *(const float4*)(w + d4);
    v.x *= r * wv.x; v.y *= r * wv.y; v.z *= r * wv.z; v.w *= r * wv.w;
    *(float4*)(p + d4) = v;
}

// ------------------------- K RMS + K/V repack to [b][kv][L][hd] -------------
__global__ __launch_bounds__(256) void kv_repack_kernel(const float* __restrict__ nk,
                                                        const float* __restrict__ nak) {
    int gw = (blockIdx.x * blockDim.x + threadIdx.x) >> 5;
    if (gw >= BSZ * NKV * LTOT) return;
    int lane = threadIdx.x & 31;
    int l = gw % LTOT;
    int bk = gw / LTOT;
    int kv = bk % NKV, b = bk / NKV;
    const float *ksrc, *vsrc, *w;
    if (l < SEQ) {
        ksrc = g_kimg + (size_t)(b * SEQ + l) * IKV + kv * HDD;
        vsrc = g_vimg + (size_t)(b * SEQ + l) * IKV + kv * HDD;
        w = nk;
    } else {
        int tt = l - SEQ;
        ksrc = g_ktxt + (size_t)(b * TXT + tt) * IKV + kv * HDD;
        vsrc = g_vtxt + (size_t)(b * TXT + tt) * IKV + kv * HDD;
        w = nak;
    }
    int d4 = lane << 2;
    float4 kvv = *(const float4*)(ksrc + d4);
    float ss = kvv.x*kvv.x + kvv.y*kvv.y + kvv.z*kvv.z + kvv.w*kvv.w;
    #pragma unroll
    for (int o = 16; o; o >>= 1) ss += __shfl_xor_sync(0xffffffffu, ss, o);
    float r = rsqrtf(ss / HDD + EPSL);
    float4 wv = *(const float4*)(w + d4);
    kvv.x *= r * wv.x; kvv.y *= r * wv.y; kvv.z *= r * wv.z; kvv.w *= r * wv.w;
    size_t dst = ((size_t)(b * NKV + kv) * LTOT + l) * HDD + d4;
    *(float4*)(g_k + dst) = kvv;
    *(float4*)(g_v + dst) = *(const float4*)(vsrc + d4);
}

// ------------------------- flash attention ----------------------------------
__global__ __launch_bounds__(256) void flash_kernel() {
    __shared__ float Qs[32][129];
    __shared__ float KVs[32][129];
    __shared__ float Ss[32][33];
    const int q0 = blockIdx.x * 32;
    const int h = blockIdx.y;
    const int b = blockIdx.z;
    const int kv = h / REP;
    const int t = threadIdx.x;
    for (int idx = t; idx < 1024; idx += 256) {
        int qi = idx >> 5, d4 = (idx & 31) << 2;
        float4 v = *(const float4*)(g_q + (size_t)(b * SEQ + q0 + qi) * DIMM + h * HDD + d4);
        Qs[qi][d4] = v.x; Qs[qi][d4+1] = v.y; Qs[qi][d4+2] = v.z; Qs[qi][d4+3] = v.w;
    }
    const int q = t >> 3, dg = t & 7;
    float acc[16];
    #pragma unroll
    for (int i = 0; i < 16; i++) acc[i] = 0.f;
    float m = -1e30f, l = 0.f;
    const float sc = 0.08838834764831845f;  // 1/sqrt(128)
    const float* kbase = g_k + (size_t)(b * NKV + kv) * LTOT * HDD;
    const float* vbase = g_v + (size_t)(b * NKV + kv) * LTOT * HDD;
    __syncthreads();
    for (int k0 = 0; k0 < LTOT; k0 += 32) {
        for (int idx = t; idx < 1024; idx += 256) {
            int ki = idx >> 5, d4 = (idx & 31) << 2;
            float4 v = *(const float4*)(kbase + (size_t)(k0 + ki) * HDD + d4);
            KVs[ki][d4] = v.x; KVs[ki][d4+1] = v.y; KVs[ki][d4+2] = v.z; KVs[ki][d4+3] = v.w;
        }
        __syncthreads();
        {
            int kb = dg << 2;
            float s0 = 0.f, s1 = 0.f, s2 = 0.f, s3 = 0.f;
            #pragma unroll 4
            for (int d = 0; d < 128; d++) {
                float qv = Qs[q][d];
                s0 += qv * KVs[kb][d];
                s1 += qv * KVs[kb+1][d];
                s2 += qv * KVs[kb+2][d];
                s3 += qv * KVs[kb+3][d];
            }
            Ss[q][kb] = s0 * sc; Ss[q][kb+1] = s1 * sc;
            Ss[q][kb+2] = s2 * sc; Ss[q][kb+3] = s3 * sc;
        }
        __syncthreads();
        float srow[32];
        float rmax = -1e30f;
        #pragma unroll
        for (int k = 0; k < 32; k++) { srow[k] = Ss[q][k]; rmax = fmaxf(rmax, srow[k]); }
        for (int idx = t; idx < 1024; idx += 256) {
            int ki = idx >> 5, d4 = (idx & 31) << 2;
            float4 v = *(const float4*)(vbase + (size_t)(k0 + ki) * HDD + d4);
            KVs[ki][d4] = v.x; KVs[ki][d4+1] = v.y; KVs[ki][d4+2] = v.z; KVs[ki][d4+3] = v.w;
        }
        float newm = fmaxf(m, rmax);
        float corr = __expf(m - newm);
        float psum = 0.f;
        #pragma unroll
        for (int k = 0; k < 32; k++) { srow[k] = __expf(srow[k] - newm); psum += srow[k]; }
        l = l * corr + psum;
        m = newm;
        #pragma unroll
        for (int i = 0; i < 16; i++) acc[i] *= corr;
        __syncthreads();
        #pragma unroll
        for (int k = 0; k < 32; k++) {
            float p = srow[k];
            #pragma unroll
            for (int i = 0; i < 16; i++) acc[i] += p * KVs[k][dg + (i << 3)];
        }
        __syncthreads();
    }
    float inv = 1.f / l;
    float* op = g_attn + (size_t)(b * SEQ + q0 + q) * DIMM + h * HDD;
    #pragma unroll
    for (int i = 0; i < 16; i++) op[dg + (i << 3)] = acc[i] * inv;
}

// ------------------------- router ------------------------------------------
__global__ __launch_bounds__(1024) void tembdot_kernel(const float* __restrict__ temb,
                                                       const float* __restrict__ Wg) {
    int wid = threadIdx.x >> 5, lane = threadIdx.x & 31;
    int b = wid / NE, e = wid % NE;
    const float* t = temb + b * DIMM;
    const float* w = Wg + (size_t)e * 2 * DIMM;
    float acc = 0.f;
    for (int d = lane; d < DIMM; d += 32) acc += t[d] * w[d];
    #pragma unroll
    for (int o = 16; o; o >>= 1) acc += __shfl_xor_sync(0xffffffffu, acc, o);
    if (lane == 0) g_tembdot[wid] = acc;
}

__global__ __launch_bounds__(128) void router_kernel(const float* __restrict__ Wg) {
    __shared__ float lg[NE];
    int tokid = blockIdx.x;
    int b = tokid >> 10, s = tokid & 1023;
    int w = threadIdx.x >> 5, lane = threadIdx.x & 31;
    const float* x = g_normed2 + (size_t)tokid * DIMM;
    for (int e = w * 4; e < w * 4 + 4; e++) {
        const float* wg = Wg + (size_t)e * 2 * DIMM + DIMM;
        float acc = 0.f;
        for (int d = lane; d < DIMM; d += 32) acc += x[d] * wg[d];
        #pragma unroll
        for (int o = 16; o; o >>= 1) acc += __shfl_xor_sync(0xffffffffu, acc, o);
        if (lane == 0) lg[e] = acc + g_tembdot[b * NE + e];
    }
    __syncthreads();
    if (threadIdx.x == 0) {
        float mx = -1e30f;
        for (int e = 0; e < NE; e++) mx = fmaxf(mx, lg[e]);
        float ex[NE], sm = 0.f;
        for (int e = 0; e < NE; e++) { ex[e] = __expf(lg[e] - mx); sm += ex[e]; }
        float inv = 1.f / sm;
        for (int e = 0; e < NE; e++)
            g_aff[((size_t)(b * NE + e)) * SEQ + s] = ex[e] * inv;
    }
}

// ------------------------- exact top-k via bitonic sort ---------------------
__global__ __launch_bounds__(512) void topk_kernel() {
    __shared__ float v[1024];
    __shared__ int   id[1024];
    int be = blockIdx.x;
    const float* rowp = g_aff + (size_t)be * SEQ;
    int t = threadIdx.x;
    for (int i = t; i < 1024; i += 512) { v[i] = rowp[i]; id[i] = i; }
    __syncthreads();
    for (int k = 2; k <= 1024; k <<= 1) {
        for (int j = k >> 1; j > 0; j >>= 1) {
            for (int i = t; i < 1024; i += 512) {
                int ixj = i ^ j;
                if (ixj > i) {
                    bool up = ((i & k) == 0);
                    float va = v[i], vb = v[ixj];
                    int ia = id[i], ib = id[ixj];
                    bool a_first = (va > vb) || (va == vb && ia < ib);
                    bool sw = up ? !a_first : a_first;
                    if (sw) { v[i] = vb; v[ixj] = va; id[i] = ib; id[ixj] = ia; }
                }
            }
            __syncthreads();
        }
    }
    if (t < CAP) {
        g_gating[be * CAP + t] = v[t];
        g_topidx[be * CAP + t] = id[t];
    }
}

__global__ void zero_sums_kernel() {
    int i = blockIdx.x * blockDim.x + threadIdx.x;
    if (i < NTOK) g_sums[i] = 0.f;
}

__global__ void sum_acc_kernel() {
    int i = blockIdx.x * blockDim.x + threadIdx.x;
    if (i >= BSZ * NE * CAP) return;
    int be = i / CAP;
    int b = be / NE;
    int tok = b * SEQ + g_topidx[i];
    atomicAdd(&g_sums[tok], g_gating[i]);
}

__global__ void gate_norm_kernel() {
    int i = blockIdx.x * blockDim.x + threadIdx.x;
    if (i >= BSZ * NE * CAP) return;
    int c = i % CAP;
    int be = i / CAP;
    int b = be / NE, e = be % NE;
    int tok = b * SEQ + g_topidx[i];
    float g = g_gating[i] / (g_sums[tok] + 1e-12f) * 2.5f;
    int rowflat = (e * BSZ + b) * CAP + c;
    g_rowmap[rowflat] = tok;
    g_rscale[rowflat] = g;
}

// ------------------------- swiglu activation --------------------------------
__global__ __launch_bounds__(256) void swiglu_kernel(const float* __restrict__ h,
                                                     float* __restrict__ out) {
    int r = blockIdx.x;
    const float4* a = (const float4*)(h + (size_t)r * 2 * NI);
    const float4* g = (const float4*)(h + (size_t)r * 2 * NI + NI);
    float4* o = (float4*)(out + (size_t)r * NI);
    for (int i = threadIdx.x; i < NI / 4; i += 256) {
        float4 av = a[i], gv = g[i], ov;
        ov.x = av.x * (gv.x / (1.f + __expf(-gv.x)));
        ov.y = av.y * (gv.y / (1.f + __expf(-gv.y)));
        ov.z = av.z * (gv.z / (1.f + __expf(-gv.z)));
        ov.w = av.w * (gv.w / (1.f + __expf(-gv.w)));
        o[i] = ov;
    }
}

// ------------------------- final residual -----------------------------------
__global__ __launch_bounds__(256) void final_kernel(float* __restrict__ out) {
    int r = blockIdx.x;
    int b = r >> 10;
    const float4* hs = (const float4*)(g_hs1 + (size_t)r * DIMM);
    const float4* mo = (const float4*)(g_outflat + (size_t)r * DIMM);
    const float4* gg = (const float4*)(g_tg2 + (size_t)b * DIMM);
    float4* o = (float4*)(out + (size_t)r * DIMM);
    for (int i = threadIdx.x; i < DIMM / 4; i += 256) {
        float4 h = hs[i], m = mo[i], g = gg[i], v;
        v.x = h.x + g.x * m.x; v.y = h.y + g.y * m.y;
        v.z = h.z + g.z * m.z; v.w = h.w + g.w * m.w;
        o[i] = v;
    }
}

// ------------------------- launcher -----------------------------------------
extern "C" void kernel_launch(void* const* d_in, const int* in_sizes, int n_in,
                              void* d_out, int out_size) {
    const float* hidden = (const float*)d_in[0];
    const float* enc    = (const float*)d_in[1];
    const float* temb   = (const float*)d_in[2];
    const float* W_mod  = (const float*)d_in[3];
    const float* b_mod  = (const float*)d_in[4];
    const float* W_enc  = (const float*)d_in[5];
    const float* b_enc  = (const float*)d_in[6];
    const float* Wq     = (const float*)d_in[7];
    const float* Wk     = (const float*)d_in[8];
    const float* Wv     = (const float*)d_in[9];
    const float* Wak    = (const float*)d_in[10];
    const float* Wav    = (const float*)d_in[11];
    const float* nq_w   = (const float*)d_in[12];
    const float* nk_w   = (const float*)d_in[13];
    const float* nak_w  = (const float*)d_in[14];
    const float* Wo     = (const float*)d_in[15];
    const float* Wg     = (const float*)d_in[16];
    const float* We_in  = (const float*)d_in[17];
    const float* We_out = (const float*)d_in[18];
    const float* Ws_in  = (const float*)d_in[19];
    const float* Ws_out = (const float*)d_in[20];
    float* out = (float*)d_out;

    void* pv;
    cudaGetSymbolAddress(&pv, g_ctx);     float* p_ctx     = (float*)pv;
    cudaGetSymbolAddress(&pv, g_imgmod);  float* p_imgmod  = (float*)pv;
    cudaGetSymbolAddress(&pv, g_q);       float* p_q       = (float*)pv;
    cudaGetSymbolAddress(&pv, g_kimg);    float* p_kimg    = (float*)pv;
    cudaGetSymbolAddress(&pv, g_vimg);    float* p_vimg    = (float*)pv;
    cudaGetSymbolAddress(&pv, g_ktxt);    float* p_ktxt    = (float*)pv;
    cudaGetSymbolAddress(&pv, g_vtxt);    float* p_vtxt    = (float*)pv;
    cudaGetSymbolAddress(&pv, g_attn);    float* p_attn    = (float*)pv;
    cudaGetSymbolAddress(&pv, g_hs1);     float* p_hs1     = (float*)pv;
    cudaGetSymbolAddress(&pv, g_mod2);    float* p_mod2    = (float*)pv;
    cudaGetSymbolAddress(&pv, g_normed2); float* p_normed2 = (float*)pv;
    cudaGetSymbolAddress(&pv, g_hmoe);    float* p_hmoe    = (float*)pv;
    cudaGetSymbolAddress(&pv, g_actmoe);  float* p_actmoe  = (float*)pv;
    cudaGetSymbolAddress(&pv, g_hsh);     float* p_hsh     = (float*)pv;
    cudaGetSymbolAddress(&pv, g_actsh);   float* p_actsh   = (float*)pv;
    cudaGetSymbolAddress(&pv, g_outflat); float* p_outflat = (float*)pv;
    cudaGetSymbolAddress(&pv, g_scale1);  float* p_scale1  = (float*)pv;
    cudaGetSymbolAddress(&pv, g_scale2);  float* p_scale2  = (float*)pv;
    cudaGetSymbolAddress(&pv, g_tg1);     float* p_tg1     = (float*)pv;
    cudaGetSymbolAddress(&pv, g_rowmap);  int*   p_rowmap  = (int*)pv;
    cudaGetSymbolAddress(&pv, g_rscale);  float* p_rscale  = (float*)pv;

    cudaFuncSetAttribute(mma_gemm<0,false>, cudaFuncAttributeMaxDynamicSharedMemorySize, MMSM);
    cudaFuncSetAttribute(mma_gemm<1,false>, cudaFuncAttributeMaxDynamicSharedMemorySize, MMSM);
    cudaFuncSetAttribute(mma_gemm<2,false>, cudaFuncAttributeMaxDynamicSharedMemorySize, MMSM);
    cudaFuncSetAttribute(mma_gemm<3,false>, cudaFuncAttributeMaxDynamicSharedMemorySize, MMSM);
    cudaFuncSetAttribute(mma_gemm<0,true>,  cudaFuncAttributeMaxDynamicSharedMemorySize, MMSM);

    const float* NFP = nullptr;
    const int*   NIP = nullptr;

    // 1. modulation
    mod_kernel<<<1536, 256>>>(temb, W_mod, b_mod);
    // 2. context projection (+bias)
    mma_gemm<1,false><<<dim3(12, 8, 1), 256, MMSM>>>(enc, W_enc, p_ctx,
        BSZ*TXT, DIMM, JD, 0, 0, 0, b_enc, NFP, NFP, NIP, NFP, NIP);
    // 3. LN1 * scale1
    ln_mod_kernel<<<NTOK, 256>>>(hidden, p_scale1, p_imgmod, nullptr);
    // 4. projections
    mma_gemm<0,false><<<dim3(12, 16, 1), 256, MMSM>>>(p_imgmod, Wq, p_q,
        NTOK, DIMM, DIMM, 0, 0, 0, NFP, NFP, NFP, NIP, NFP, NIP);
    mma_gemm<0,false><<<dim3(4, 16, 1), 256, MMSM>>>(p_imgmod, Wk, p_kimg,
        NTOK, IKV, DIMM, 0, 0, 0, NFP, NFP, NFP, NIP, NFP, NIP);
    mma_gemm<0,false><<<dim3(4, 16, 1), 256, MMSM>>>(p_imgmod, Wv, p_vimg,
        NTOK, IKV, DIMM, 0, 0, 0, NFP, NFP, NFP, NIP, NFP, NIP);
    mma_gemm<0,false><<<dim3(4, 8, 1), 256, MMSM>>>(p_ctx, Wak, p_ktxt,
        BSZ*TXT, IKV, DIMM, 0, 0, 0, NFP, NFP, NFP, NIP, NFP, NIP);
    mma_gemm<0,false><<<dim3(4, 8, 1), 256, MMSM>>>(p_ctx, Wav, p_vtxt,
        BSZ*TXT, IKV, DIMM, 0, 0, 0, NFP, NFP, NFP, NIP, NFP, NIP);
    // 5. norms + repack
    rms_q_kernel<<<3072, 256>>>(nq_w);
    kv_repack_kernel<<<1536, 256>>>(nk_w, nak_w);
    // 6. attention
    flash_kernel<<<dim3(SEQ/32, NH, BSZ), 256>>>();
    // 7. output proj + gated residual
    mma_gemm<2,false><<<dim3(12, 16, 1), 256, MMSM>>>(p_attn, Wo, p_hs1,
        NTOK, DIMM, DIMM, 0, 0, 0, NFP, hidden, p_tg1, NIP, NFP, NIP);
    // 8. LN2
    ln_mod_kernel<<<NTOK, 256>>>(p_hs1, p_scale2, p_mod2, p_normed2);
    // 9. router
    tembdot_kernel<<<1, 1024>>>(temb, Wg);
    router_kernel<<<NTOK, 128>>>(Wg);
    topk_kernel<<<BSZ*NE, 512>>>();
    zero_sums_kernel<<<8, 256>>>();
    sum_acc_kernel<<<64, 256>>>();
    gate_norm_kernel<<<64, 256>>>();
    // 10. expert GEMM 1 (gathered A rows, batched over 16 experts)
    mma_gemm<0,true><<<dim3(21, 8, 16), 256, MMSM>>>(p_mod2, We_in, p_hmoe,
        BSZ*CAP, 2*NI, DIMM,
        0, (long long)2*NI*DIMM, (long long)BSZ*CAP*2*NI,
        NFP, NFP, NFP, NIP, NFP, p_rowmap);
    swiglu_kernel<<<MROWS, 256>>>(p_hmoe, p_actmoe);
    // 11. shared expert
    mma_gemm<0,false><<<dim3(21, 16, 1), 256, MMSM>>>(p_mod2, Ws_in, p_hsh,
        NTOK, 2*NI, DIMM, 0, 0, 0, NFP, NFP, NFP, NIP, NFP, NIP);
    swiglu_kernel<<<NTOK, 256>>>(p_hsh, p_actsh);
    mma_gemm<0,false><<<dim3(12, 16, 1), 256, MMSM>>>(p_actsh, Ws_out, p_outflat,
        NTOK, DIMM, NI, 0, 0, 0, NFP, NFP, NFP, NIP, NFP, NIP);
    // 12. expert GEMM 2 with atomic scatter onto shared output
    mma_gemm<3,false><<<dim3(12, 8, 16), 256, MMSM>>>(p_actmoe, We_out, p_outflat,
        BSZ*CAP, DIMM, NI,
        (long long)BSZ*CAP*NI, (long long)DIMM*NI, 0,
        NFP, NFP, NFP, p_rowmap, p_rscale, NIP);
    // 13. final gated residual
    final_kernel<<<NTOK, 256>>>(out);
}

// round 8
// speedup vs baseline: 1.0400x; 1.0400x over previous
#include <cuda_runtime.h>
#include <cuda_fp16.h>
#include <math.h>
#include <stdint.h>

#define BSZ 2
#define SEQ 1024
#define TXT 512
#define DIMM 1536
#define NH 12
#define HDD 128
#define NKV 4
#define JD 3584
#define NE 16
#define NI 1344
#define CAP 512
#define LTOT 1536      // SEQ + TXT
#define NTOK 2048      // BSZ*SEQ
#define MROWS 16384    // NE*BSZ*CAP
#define IKV 512        // NKV*HDD
#define REP 3          // NH/NKV
#define EPSL 1e-6f

// ------------------------- scratch (device globals) -------------------------
__device__ float g_scale1[BSZ*DIMM];
__device__ float g_tg1[BSZ*DIMM];
__device__ float g_scale2[BSZ*DIMM];
__device__ float g_tg2[BSZ*DIMM];
__device__ float g_ctx[BSZ*TXT*DIMM];
__device__ float g_imgmod[NTOK*DIMM];
__device__ float g_q[NTOK*DIMM];
__device__ float g_kimg[NTOK*IKV];
__device__ float g_vimg[NTOK*IKV];
__device__ float g_ktxt[BSZ*TXT*IKV];
__device__ float g_vtxt[BSZ*TXT*IKV];
__device__ float g_k[BSZ*NKV*LTOT*HDD];
__device__ float g_v[BSZ*NKV*LTOT*HDD];
__device__ float g_attn[NTOK*DIMM];
__device__ float g_hs1[NTOK*DIMM];
__device__ float g_normed2[NTOK*DIMM];
__device__ float g_mod2[NTOK*DIMM];
__device__ float g_tembdot[BSZ*NE];
__device__ float g_aff[BSZ*NE*SEQ];
__device__ int   g_topidx[BSZ*NE*CAP];
__device__ float g_gating[BSZ*NE*CAP];
__device__ float g_sums[NTOK];
__device__ int   g_rowmap[MROWS];
__device__ float g_rscale[MROWS];
__device__ float g_hmoe[(size_t)MROWS*2*NI];
__device__ float g_actmoe[(size_t)MROWS*NI];
__device__ float g_hsh[NTOK*2*NI];
__device__ float g_actsh[NTOK*NI];
__device__ float g_outflat[NTOK*DIMM];

// ======================= helpers ============================================
__device__ __forceinline__ uint32_t s2u(const void* p) {
    uint32_t a;
    asm("{ .reg .u64 t; cvta.to.shared.u64 t, %1; cvt.u32.u64 %0, t; }"
        : "=r"(a) : "l"(p));
    return a;
}
__device__ __forceinline__ void ld16(const float* __restrict__ p, float* d) {
    #pragma unroll
    for (int i = 0; i < 4; i++) *(float4*)(d + 4*i) = *(const float4*)(p + 4*i);
}
// 16 fp32 -> hi/lo fp16 split, packed as 2+2 uint4
__device__ __forceinline__ void cvt16(const float* f, uint4* hs, uint4* ls) {
    union { __half h[16]; uint4 u[2]; } H, L;
    #pragma unroll
    for (int i = 0; i < 16; i++) {
        __half hh = __float2half(f[i]);
        H.h[i] = hh;
        L.h[i] = __float2half(f[i] - __half2float(hh));
    }
    hs[0] = H.u[0]; hs[1] = H.u[1];
    ls[0] = L.u[0]; ls[1] = L.u[1];
}
__device__ __forceinline__ void mma16816(float* c, const uint32_t* a, const uint32_t* b) {
    asm volatile(
        "mma.sync.aligned.m16n8k16.row.col.f32.f16.f16.f32 "
        "{%0,%1,%2,%3}, {%4,%5,%6,%7}, {%8,%9}, {%0,%1,%2,%3};"
        : "+f"(c[0]), "+f"(c[1]), "+f"(c[2]), "+f"(c[3])
        : "r"(a[0]), "r"(a[1]), "r"(a[2]), "r"(a[3]), "r"(b[0]), "r"(b[1]));
}

// ======================= split-fp16 mma.sync GEMM ===========================
// C[M,N] = A[M,K] * B[N,K]^T at ~fp32 precision via 3-term f16 split with
// REGISTER REUSE (no smem duplication):
//   acc += Ah*Bh + Ah*Bl + Al*Bh   (Al*Bl ~ 2^-22, dropped)
// SMEM: 4 planes (Ah, Al, Bh, Bl), 128 rows x 64B, stride 80B (LDSM
// conflict-free). CTA tile 128x128, source-K chunk 32, 8 warps (2x4),
// warp tile 64x32. Register prefetch of next chunk overlaps MMA.
// EPI 0: store  1: +bias[n]  2: resid + gate[b][n]*acc  3: atomic scatter
// AG: gather A rows through agather[z*M + m].
#define PRS 80                  // plane row stride (bytes)
#define PLSZ (128*PRS)          // 10240
#define MMSM (4*PLSZ)           // 40960

template<int EPI, bool AG>
__global__ __launch_bounds__(256, 2) void mma_gemm(
    const float* __restrict__ A, const float* __restrict__ B, float* __restrict__ C,
    int M, int N, int K,
    long long sA, long long sB, long long sC,
    const float* __restrict__ bias,
    const float* __restrict__ resid, const float* __restrict__ gate,
    const int* __restrict__ rowmap, const float* __restrict__ rscale,
    const int* __restrict__ agather)
{
    extern __shared__ char smem[];
    char* plAh = smem;
    char* plAl = smem + PLSZ;
    char* plBh = smem + 2*PLSZ;
    char* plBl = smem + 3*PLSZ;
    const int tid = threadIdx.x;
    const int wid = tid >> 5, lane = tid & 31;
    const int z = blockIdx.z;
    const int m0 = blockIdx.y * 128, n0 = blockIdx.x * 128;
    if (!AG) A += (long long)z * sA;
    B += (long long)z * sB;

    // ---- loader assignment: thread owns row lr, k16-half lh ----
    const int lr = tid >> 1;
    const int lh = tid & 1;
    long long arow = AG ? (long long)agather[(long long)z * M + m0 + lr]
                        : (long long)(m0 + lr);
    const float* ag = A + arow * (long long)K + lh * 16;
    const float* bg = B + (long long)(n0 + lr) * K + lh * 16;
    const int pofs = lr * PRS + lh * 32;

    // ---- warp tile / ldmatrix addresses ----
    const int wm = (wid >> 2) * 64;
    const int wn = (wid & 3) * 32;
    const uint32_t uAh = s2u(plAh), uAl = s2u(plAl);
    const uint32_t uBh = s2u(plBh), uBl = s2u(plBl);
    uint32_t a_off[4];
    #pragma unroll
    for (int mt = 0; mt < 4; mt++) {
        int r = wm + mt * 16 + (lane & 15);
        a_off[mt] = r * PRS + (lane >> 4) * 16;
    }
    uint32_t b_off[2];
    #pragma unroll
    for (int np = 0; np < 2; np++) {
        int r = wn + np * 16 + ((lane >> 4) << 3) + (lane & 7);
        b_off[np] = r * PRS + ((lane >> 3) & 1) * 16;
    }

    float acc[4][4][4];
    #pragma unroll
    for (int mt = 0; mt < 4; mt++)
        #pragma unroll
        for (int nt = 0; nt < 4; nt++)
            #pragma unroll
            for (int i = 0; i < 4; i++) acc[mt][nt][i] = 0.f;

    const int NC = K >> 5;
    float pfa[16], pfb[16];
    ld16(ag, pfa);
    ld16(bg, pfb);

    for (int c = 0; c < NC; c++) {
        if (c) __syncthreads();           // compute of c-1 done reading planes
        {
            uint4 h[2], l[2];
            cvt16(pfa, h, l);
            *(uint4*)(plAh + pofs) = h[0]; *(uint4*)(plAh + pofs + 16) = h[1];
            *(uint4*)(plAl + pofs) = l[0]; *(uint4*)(plAl + pofs + 16) = l[1];
            cvt16(pfb, h, l);
            *(uint4*)(plBh + pofs) = h[0]; *(uint4*)(plBh + pofs + 16) = h[1];
            *(uint4*)(plBl + pofs) = l[0]; *(uint4*)(plBl + pofs + 16) = l[1];
        }
        __syncthreads();
        if (c + 1 < NC) {                 // prefetch next chunk (overlaps MMA)
            ld16(ag + (c + 1) * 32, pfa);
            ld16(bg + (c + 1) * 32, pfb);
        }
        #pragma unroll
        for (int ks = 0; ks < 2; ks++) {
            uint32_t bh[4][2], bl[4][2];
            #pragma unroll
            for (int np = 0; np < 2; np++) {
                asm volatile("ldmatrix.sync.aligned.m8n8.x4.shared.b16 {%0,%1,%2,%3}, [%4];"
                    : "=r"(bh[np*2][0]), "=r"(bh[np*2][1]),
                      "=r"(bh[np*2+1][0]), "=r"(bh[np*2+1][1])
                    : "r"(uBh + b_off[np] + ks * 32));
                asm volatile("ldmatrix.sync.aligned.m8n8.x4.shared.b16 {%0,%1,%2,%3}, [%4];"
                    : "=r"(bl[np*2][0]), "=r"(bl[np*2][1]),
                      "=r"(bl[np*2+1][0]), "=r"(bl[np*2+1][1])
                    : "r"(uBl + b_off[np] + ks * 32));
            }
            #pragma unroll
            for (int mt = 0; mt < 4; mt++) {
                uint32_t ah[4], al[4];
                asm volatile("ldmatrix.sync.aligned.m8n8.x4.shared.b16 {%0,%1,%2,%3}, [%4];"
                    : "=r"(ah[0]), "=r"(ah[1]), "=r"(ah[2]), "=r"(ah[3])
                    : "r"(uAh + a_off[mt] + ks * 32));
                asm volatile("ldmatrix.sync.aligned.m8n8.x4.shared.b16 {%0,%1,%2,%3}, [%4];"
                    : "=r"(al[0]), "=r"(al[1]), "=r"(al[2]), "=r"(al[3])
                    : "r"(uAl + a_off[mt] + ks * 32));
                #pragma unroll
                for (int nt = 0; nt < 4; nt++) mma16816(acc[mt][nt], ah, bh[nt]);
                #pragma unroll
                for (int nt = 0; nt < 4; nt++) mma16816(acc[mt][nt], ah, bl[nt]);
                #pragma unroll
                for (int nt = 0; nt < 4; nt++) mma16816(acc[mt][nt], al, bh[nt]);
            }
        }
    }

    // ---- epilogue ----
    const int g = lane >> 2;
    const int cp2 = (lane & 3) * 2;
    #pragma unroll
    for (int mt = 0; mt < 4; mt++) {
        #pragma unroll
        for (int hh = 0; hh < 2; hh++) {
            int row = m0 + wm + mt * 16 + g + hh * 8;
            if (EPI == 3) {
                long long gr = (long long)z * M + row;
                int trow = rowmap[gr];
                float s = rscale[gr];
                float* cp = C + (long long)trow * N;
                #pragma unroll
                for (int nt = 0; nt < 4; nt++) {
                    int col = n0 + wn + nt * 8 + cp2;
                    atomicAdd(cp + col,     acc[mt][nt][hh*2]   * s);
                    atomicAdd(cp + col + 1, acc[mt][nt][hh*2+1] * s);
                }
            } else {
                float* Cz = C + (long long)z * sC + (long long)row * N;
                #pragma unroll
                for (int nt = 0; nt < 4; nt++) {
                    int col = n0 + wn + nt * 8 + cp2;
                    float v0 = acc[mt][nt][hh*2], v1 = acc[mt][nt][hh*2+1];
                    if (EPI == 1) { v0 += bias[col]; v1 += bias[col + 1]; }
                    if (EPI == 2) {
                        const float* gp = gate + (row / SEQ) * N + col;
                        const float* rp = resid + (long long)row * N + col;
                        v0 = rp[0] + gp[0] * v0;
                        v1 = rp[1] + gp[1] * v1;
                    }
                    *(float2*)(Cz + col) = make_float2(v0, v1);
                }
            }
        }
    }
}

// ------------------------- modulation: mod = silu(temb) @ W_mod^T + b -------
__global__ __launch_bounds__(256) void mod_kernel(const float* __restrict__ temb,
                                                  const float* __restrict__ Wm,
                                                  const float* __restrict__ bm) {
    int gw = (blockIdx.x * blockDim.x + threadIdx.x) >> 5;
    int lane = threadIdx.x & 31;
    if (gw >= BSZ * 4 * DIMM) return;
    int b = gw / (4 * DIMM);
    int j = gw - b * 4 * DIMM;
    const float* t = temb + b * DIMM;
    const float* w = Wm + (size_t)j * DIMM;
    float acc = 0.f;
    for (int kk = lane; kk < DIMM; kk += 32) {
        float x = t[kk];
        acc += (x / (1.f + __expf(-x))) * w[kk];
    }
    #pragma unroll
    for (int o = 16; o; o >>= 1) acc += __shfl_xor_sync(0xffffffffu, acc, o);
    if (lane == 0) {
        acc += bm[j];
        int q = j / DIMM, c = j - q * DIMM;
        if (q == 0)      g_scale1[b*DIMM + c] = 1.f + acc;
        else if (q == 1) g_tg1[b*DIMM + c]    = tanhf(fminf(fmaxf(acc, -2.f), 2.f));
        else if (q == 2) g_scale2[b*DIMM + c] = 1.f + acc;
        else             g_tg2[b*DIMM + c]    = tanhf(fminf(fmaxf(acc, -2.f), 2.f));
    }
}

// ------------------------- LayerNorm (+ scale, optional normed out) ---------
__global__ __launch_bounds__(256) void ln_mod_kernel(const float* __restrict__ in,
                                                     const float* __restrict__ scale,
                                                     float* __restrict__ outmod,
                                                     float* __restrict__ outnorm) {
    int rowi = blockIdx.x;
    int b = rowi >> 10;
    const float* x = in + (size_t)rowi * DIMM;
    float s = 0.f, sq = 0.f;
    for (int d = threadIdx.x; d < DIMM; d += 256) { float v = x[d]; s += v; sq += v * v; }
    #pragma unroll
    for (int o = 16; o; o >>= 1) {
        s  += __shfl_xor_sync(0xffffffffu, s,  o);
        sq += __shfl_xor_sync(0xffffffffu, sq, o);
    }
    __shared__ float rs[8], rq[8], mv[2];
    int w = threadIdx.x >> 5;
    if ((threadIdx.x & 31) == 0) { rs[w] = s; rq[w] = sq; }
    __syncthreads();
    if (threadIdx.x == 0) {
        float S = 0.f, Q = 0.f;
        for (int i = 0; i < 8; i++) { S += rs[i]; Q += rq[i]; }
        float mean = S / DIMM;
        float var = Q / DIMM - mean * mean;
        mv[0] = mean; mv[1] = rsqrtf(var + EPSL);
    }
    __syncthreads();
    float mean = mv[0], rstd = mv[1];
    const float* sc = scale + (size_t)b * DIMM;
    for (int d = threadIdx.x; d < DIMM; d += 256) {
        float n = (x[d] - mean) * rstd;
        if (outnorm) outnorm[(size_t)rowi * DIMM + d] = n;
        outmod[(size_t)rowi * DIMM + d] = n * sc[d];
    }
}

// ------------------------- per-head RMSNorm of Q ----------------------------
__global__ __launch_bounds__(256) void rms_q_kernel(const float* __restrict__ w) {
    int gw = (blockIdx.x * blockDim.x + threadIdx.x) >> 5;
    if (gw >= NTOK * NH) return;
    int lane = threadIdx.x & 31;
    float* p = g_q + (size_t)gw * HDD;
    int d4 = lane << 2;
    float4 v = *(float4*)(p + d4);
    float ss = v.x*v.x + v.y*v.y + v.z*v.z + v.w*v.w;
    #pragma unroll
    for (int o = 16; o; o >>= 1) ss += __shfl_xor_sync(0xffffffffu, ss, o);
    float r = rsqrtf(ss / HDD + EPSL);
    float4 wv = *(const float4*)(w + d4);
    v.x *= r * wv.x; v.y *= r * wv.y; v.z *= r * wv.z; v.w *= r * wv.w;
    *(float4*)(p + d4) = v;
}

// ------------------------- K RMS + K/V repack to [b][kv][L][hd] -------------
__global__ __launch_bounds__(256) void kv_repack_kernel(const float* __restrict__ nk,
                                                        const float* __restrict__ nak) {
    int gw = (blockIdx.x * blockDim.x + threadIdx.x) >> 5;
    if (gw >= BSZ * NKV * LTOT) return;
    int lane = threadIdx.x & 31;
    int l = gw % LTOT;
    int bk = gw / LTOT;
    int kv = bk % NKV, b = bk / NKV;
    const float *ksrc, *vsrc, *w;
    if (l < SEQ) {
        ksrc = g_kimg + (size_t)(b * SEQ + l) * IKV + kv * HDD;
        vsrc = g_vimg + (size_t)(b * SEQ + l) * IKV + kv * HDD;
        w = nk;
    } else {
        int tt = l - SEQ;
        ksrc = g_ktxt + (size_t)(b * TXT + tt) * IKV + kv * HDD;
        vsrc = g_vtxt + (size_t)(b * TXT + tt) * IKV + kv * HDD;
        w = nak;
    }
    int d4 = lane << 2;
    float4 kvv = *(const float4*)(ksrc + d4);
    float ss = kvv.x*kvv.x + kvv.y*kvv.y + kvv.z*kvv.z + kvv.w*kvv.w;
    #pragma unroll
    for (int o = 16; o; o >>= 1) ss += __shfl_xor_sync(0xffffffffu, ss, o);
    float r = rsqrtf(ss / HDD + EPSL);
    float4 wv = *(const float4*)(w + d4);
    kvv.x *= r * wv.x; kvv.y *= r * wv.y; kvv.z *= r * wv.z; kvv.w *= r * wv.w;
    size_t dst = ((size_t)(b * NKV + kv) * LTOT + l) * HDD + d4;
    *(float4*)(g_k + dst) = kvv;
    *(float4*)(g_v + dst) = *(const float4*)(vsrc + d4);
}

// ------------------------- flash attention ----------------------------------
__global__ __launch_bounds__(256) void flash_kernel() {
    __shared__ float Qs[32][129];
    __shared__ float KVs[32][129];
    __shared__ float Ss[32][33];
    const int q0 = blockIdx.x * 32;
    const int h = blockIdx.y;
    const int b = blockIdx.z;
    const int kv = h / REP;
    const int t = threadIdx.x;
    for (int idx = t; idx < 1024; idx += 256) {
        int qi = idx >> 5, d4 = (idx & 31) << 2;
        float4 v = *(const float4*)(g_q + (size_t)(b * SEQ + q0 + qi) * DIMM + h * HDD + d4);
        Qs[qi][d4] = v.x; Qs[qi][d4+1] = v.y; Qs[qi][d4+2] = v.z; Qs[qi][d4+3] = v.w;
    }
    const int q = t >> 3, dg = t & 7;
    float acc[16];
    #pragma unroll
    for (int i = 0; i < 16; i++) acc[i] = 0.f;
    float m = -1e30f, l = 0.f;
    const float sc = 0.08838834764831845f;  // 1/sqrt(128)
    const float* kbase = g_k + (size_t)(b * NKV + kv) * LTOT * HDD;
    const float* vbase = g_v + (size_t)(b * NKV + kv) * LTOT * HDD;
    __syncthreads();
    for (int k0 = 0; k0 < LTOT; k0 += 32) {
        for (int idx = t; idx < 1024; idx += 256) {
            int ki = idx >> 5, d4 = (idx & 31) << 2;
            float4 v = *(const float4*)(kbase + (size_t)(k0 + ki) * HDD + d4);
            KVs[ki][d4] = v.x; KVs[ki][d4+1] = v.y; KVs[ki][d4+2] = v.z; KVs[ki][d4+3] = v.w;
        }
        __syncthreads();
        {
            int kb = dg << 2;
            float s0 = 0.f, s1 = 0.f, s2 = 0.f, s3 = 0.f;
            #pragma unroll 4
            for (int d = 0; d < 128; d++) {
                float qv = Qs[q][d];
                s0 += qv * KVs[kb][d];
                s1 += qv * KVs[kb+1][d];
                s2 += qv * KVs[kb+2][d];
                s3 += qv * KVs[kb+3][d];
            }
            Ss[q][kb] = s0 * sc; Ss[q][kb+1] = s1 * sc;
            Ss[q][kb+2] = s2 * sc; Ss[q][kb+3] = s3 * sc;
        }
        __syncthreads();
        float srow[32];
        float rmax = -1e30f;
        #pragma unroll
        for (int k = 0; k < 32; k++) { srow[k] = Ss[q][k]; rmax = fmaxf(rmax, srow[k]); }
        for (int idx = t; idx < 1024; idx += 256) {
            int ki = idx >> 5, d4 = (idx & 31) << 2;
            float4 v = *(const float4*)(vbase + (size_t)(k0 + ki) * HDD + d4);
            KVs[ki][d4] = v.x; KVs[ki][d4+1] = v.y; KVs[ki][d4+2] = v.z; KVs[ki][d4+3] = v.w;
        }
        float newm = fmaxf(m, rmax);
        float corr = __expf(m - newm);
        float psum = 0.f;
        #pragma unroll
        for (int k = 0; k < 32; k++) { srow[k] = __expf(srow[k] - newm); psum += srow[k]; }
        l = l * corr + psum;
        m = newm;
        #pragma unroll
        for (int i = 0; i < 16; i++) acc[i] *= corr;
        __syncthreads();
        #pragma unroll
        for (int k = 0; k < 32; k++) {
            float p = srow[k];
            #pragma unroll
            for (int i = 0; i < 16; i++) acc[i] += p * KVs[k][dg + (i << 3)];
        }
        __syncthreads();
    }
    float inv = 1.f / l;
    float* op = g_attn + (size_t)(b * SEQ + q0 + q) * DIMM + h * HDD;
    #pragma unroll
    for (int i = 0; i < 16; i++) op[dg + (i << 3)] = acc[i] * inv;
}

// ------------------------- router ------------------------------------------
__global__ __launch_bounds__(1024) void tembdot_kernel(const float* __restrict__ temb,
                                                       const float* __restrict__ Wg) {
    int wid = threadIdx.x >> 5, lane = threadIdx.x & 31;
    int b = wid / NE, e = wid % NE;
    const float* t = temb + b * DIMM;
    const float* w = Wg + (size_t)e * 2 * DIMM;
    float acc = 0.f;
    for (int d = lane; d < DIMM; d += 32) acc += t[d] * w[d];
    #pragma unroll
    for (int o = 16; o; o >>= 1) acc += __shfl_xor_sync(0xffffffffu, acc, o);
    if (lane == 0) g_tembdot[wid] = acc;
}

__global__ __launch_bounds__(128) void router_kernel(const float* __restrict__ Wg) {
    __shared__ float lg[NE];
    int tokid = blockIdx.x;
    int b = tokid >> 10, s = tokid & 1023;
    int w = threadIdx.x >> 5, lane = threadIdx.x & 31;
    const float* x = g_normed2 + (size_t)tokid * DIMM;
    for (int e = w * 4; e < w * 4 + 4; e++) {
        const float* wg = Wg + (size_t)e * 2 * DIMM + DIMM;
        float acc = 0.f;
        for (int d = lane; d < DIMM; d += 32) acc += x[d] * wg[d];
        #pragma unroll
        for (int o = 16; o; o >>= 1) acc += __shfl_xor_sync(0xffffffffu, acc, o);
        if (lane == 0) lg[e] = acc + g_tembdot[b * NE + e];
    }
    __syncthreads();
    if (threadIdx.x == 0) {
        float mx = -1e30f;
        for (int e = 0; e < NE; e++) mx = fmaxf(mx, lg[e]);
        float ex[NE], sm = 0.f;
        for (int e = 0; e < NE; e++) { ex[e] = __expf(lg[e] - mx); sm += ex[e]; }
        float inv = 1.f / sm;
        for (int e = 0; e < NE; e++)
            g_aff[((size_t)(b * NE + e)) * SEQ + s] = ex[e] * inv;
    }
}

// ------------------------- exact top-k via bitonic sort ---------------------
__global__ __launch_bounds__(512) void topk_kernel() {
    __shared__ float v[1024];
    __shared__ int   id[1024];
    int be = blockIdx.x;
    const float* rowp = g_aff + (size_t)be * SEQ;
    int t = threadIdx.x;
    for (int i = t; i < 1024; i += 512) { v[i] = rowp[i]; id[i] = i; }
    __syncthreads();
    for (int k = 2; k <= 1024; k <<= 1) {
        for (int j = k >> 1; j > 0; j >>= 1) {
            for (int i = t; i < 1024; i += 512) {
                int ixj = i ^ j;
                if (ixj > i) {
                    bool up = ((i & k) == 0);
                    float va = v[i], vb = v[ixj];
                    int ia = id[i], ib = id[ixj];
                    bool a_first = (va > vb) || (va == vb && ia < ib);
                    bool sw = up ? !a_first : a_first;
                    if (sw) { v[i] = vb; v[ixj] = va; id[i] = ib; id[ixj] = ia; }
                }
            }
            __syncthreads();
        }
    }
    if (t < CAP) {
        g_gating[be * CAP + t] = v[t];
        g_topidx[be * CAP + t] = id[t];
    }
}

__global__ void zero_sums_kernel() {
    int i = blockIdx.x * blockDim.x + threadIdx.x;
    if (i < NTOK) g_sums[i] = 0.f;
}

__global__ void sum_acc_kernel() {
    int i = blockIdx.x * blockDim.x + threadIdx.x;
    if (i >= BSZ * NE * CAP) return;
    int be = i / CAP;
    int b = be / NE;
    int tok = b * SEQ + g_topidx[i];
    atomicAdd(&g_sums[tok], g_gating[i]);
}

__global__ void gate_norm_kernel() {
    int i = blockIdx.x * blockDim.x + threadIdx.x;
    if (i >= BSZ * NE * CAP) return;
    int c = i % CAP;
    int be = i / CAP;
    int b = be / NE, e = be % NE;
    int tok = b * SEQ + g_topidx[i];
    float g = g_gating[i] / (g_sums[tok] + 1e-12f) * 2.5f;
    int rowflat = (e * BSZ + b) * CAP + c;
    g_rowmap[rowflat] = tok;
    g_rscale[rowflat] = g;
}

// ------------------------- swiglu activation --------------------------------
__global__ __launch_bounds__(256) void swiglu_kernel(const float* __restrict__ h,
                                                     float* __restrict__ out) {
    int r = blockIdx.x;
    const float4* a = (const float4*)(h + (size_t)r * 2 * NI);
    const float4* g = (const float4*)(h + (size_t)r * 2 * NI + NI);
    float4* o = (float4*)(out + (size_t)r * NI);
    for (int i = threadIdx.x; i < NI / 4; i += 256) {
        float4 av = a[i], gv = g[i], ov;
        ov.x = av.x * (gv.x / (1.f + __expf(-gv.x)));
        ov.y = av.y * (gv.y / (1.f + __expf(-gv.y)));
        ov.z = av.z * (gv.z / (1.f + __expf(-gv.z)));
        ov.w = av.w * (gv.w / (1.f + __expf(-gv.w)));
        o[i] = ov;
    }
}

// ------------------------- final residual -----------------------------------
__global__ __launch_bounds__(256) void final_kernel(float* __restrict__ out) {
    int r = blockIdx.x;
    int b = r >> 10;
    const float4* hs = (const float4*)(g_hs1 + (size_t)r * DIMM);
    const float4* mo = (const float4*)(g_outflat + (size_t)r * DIMM);
    const float4* gg = (const float4*)(g_tg2 + (size_t)b * DIMM);
    float4* o = (float4*)(out + (size_t)r * DIMM);
    for (int i = threadIdx.x; i < DIMM / 4; i += 256) {
        float4 h = hs[i], m = mo[i], g = gg[i], v;
        v.x = h.x + g.x * m.x; v.y = h.y + g.y * m.y;
        v.z = h.z + g.z * m.z; v.w = h.w + g.w * m.w;
        o[i] = v;
    }
}

// ------------------------- launcher -----------------------------------------
extern "C" void kernel_launch(void* const* d_in, const int* in_sizes, int n_in,
                              void* d_out, int out_size) {
    const float* hidden = (const float*)d_in[0];
    const float* enc    = (const float*)d_in[1];
    const float* temb   = (const float*)d_in[2];
    const float* W_mod  = (const float*)d_in[3];
    const float* b_mod  = (const float*)d_in[4];
    const float* W_enc  = (const float*)d_in[5];
    const float* b_enc  = (const float*)d_in[6];
    const float* Wq     = (const float*)d_in[7];
    const float* Wk     = (const float*)d_in[8];
    const float* Wv     = (const float*)d_in[9];
    const float* Wak    = (const float*)d_in[10];
    const float* Wav    = (const float*)d_in[11];
    const float* nq_w   = (const float*)d_in[12];
    const float* nk_w   = (const float*)d_in[13];
    const float* nak_w  = (const float*)d_in[14];
    const float* Wo     = (const float*)d_in[15];
    const float* Wg     = (const float*)d_in[16];
    const float* We_in  = (const float*)d_in[17];
    const float* We_out = (const float*)d_in[18];
    const float* Ws_in  = (const float*)d_in[19];
    const float* Ws_out = (const float*)d_in[20];
    float* out = (float*)d_out;

    void* pv;
    cudaGetSymbolAddress(&pv, g_ctx);     float* p_ctx     = (float*)pv;
    cudaGetSymbolAddress(&pv, g_imgmod);  float* p_imgmod  = (float*)pv;
    cudaGetSymbolAddress(&pv, g_q);       float* p_q       = (float*)pv;
    cudaGetSymbolAddress(&pv, g_kimg);    float* p_kimg    = (float*)pv;
    cudaGetSymbolAddress(&pv, g_vimg);    float* p_vimg    = (float*)pv;
    cudaGetSymbolAddress(&pv, g_ktxt);    float* p_ktxt    = (float*)pv;
    cudaGetSymbolAddress(&pv, g_vtxt);    float* p_vtxt    = (float*)pv;
    cudaGetSymbolAddress(&pv, g_attn);    float* p_attn    = (float*)pv;
    cudaGetSymbolAddress(&pv, g_hs1);     float* p_hs1     = (float*)pv;
    cudaGetSymbolAddress(&pv, g_mod2);    float* p_mod2    = (float*)pv;
    cudaGetSymbolAddress(&pv, g_normed2); float* p_normed2 = (float*)pv;
    cudaGetSymbolAddress(&pv, g_hmoe);    float* p_hmoe    = (float*)pv;
    cudaGetSymbolAddress(&pv, g_actmoe);  float* p_actmoe  = (float*)pv;
    cudaGetSymbolAddress(&pv, g_hsh);     float* p_hsh     = (float*)pv;
    cudaGetSymbolAddress(&pv, g_actsh);   float* p_actsh   = (float*)pv;
    cudaGetSymbolAddress(&pv, g_outflat); float* p_outflat = (float*)pv;
    cudaGetSymbolAddress(&pv, g_scale1);  float* p_scale1  = (float*)pv;
    cudaGetSymbolAddress(&pv, g_scale2);  float* p_scale2  = (float*)pv;
    cudaGetSymbolAddress(&pv, g_tg1);     float* p_tg1     = (float*)pv;
    cudaGetSymbolAddress(&pv, g_rowmap);  int*   p_rowmap  = (int*)pv;
    cudaGetSymbolAddress(&pv, g_rscale);  float* p_rscale  = (float*)pv;

    const float* NFP = nullptr;
    const int*   NIP = nullptr;

    // 1. modulation
    mod_kernel<<<1536, 256>>>(temb, W_mod, b_mod);
    // 2. context projection (+bias)
    mma_gemm<1,false><<<dim3(12, 8, 1), 256, MMSM>>>(enc, W_enc, p_ctx,
        BSZ*TXT, DIMM, JD, 0, 0, 0, b_enc, NFP, NFP, NIP, NFP, NIP);
    // 3. LN1 * scale1
    ln_mod_kernel<<<NTOK, 256>>>(hidden, p_scale1, p_imgmod, nullptr);
    // 4. projections
    mma_gemm<0,false><<<dim3(12, 16, 1), 256, MMSM>>>(p_imgmod, Wq, p_q,
        NTOK, DIMM, DIMM, 0, 0, 0, NFP, NFP, NFP, NIP, NFP, NIP);
    mma_gemm<0,false><<<dim3(4, 16, 1), 256, MMSM>>>(p_imgmod, Wk, p_kimg,
        NTOK, IKV, DIMM, 0, 0, 0, NFP, NFP, NFP, NIP, NFP, NIP);
    mma_gemm<0,false><<<dim3(4, 16, 1), 256, MMSM>>>(p_imgmod, Wv, p_vimg,
        NTOK, IKV, DIMM, 0, 0, 0, NFP, NFP, NFP, NIP, NFP, NIP);
    mma_gemm<0,false><<<dim3(4, 8, 1), 256, MMSM>>>(p_ctx, Wak, p_ktxt,
        BSZ*TXT, IKV, DIMM, 0, 0, 0, NFP, NFP, NFP, NIP, NFP, NIP);
    mma_gemm<0,false><<<dim3(4, 8, 1), 256, MMSM>>>(p_ctx, Wav, p_vtxt,
        BSZ*TXT, IKV, DIMM, 0, 0, 0, NFP, NFP, NFP, NIP, NFP, NIP);
    // 5. norms + repack
    rms_q_kernel<<<3072, 256>>>(nq_w);
    kv_repack_kernel<<<1536, 256>>>(nk_w, nak_w);
    // 6. attention
    flash_kernel<<<dim3(SEQ/32, NH, BSZ), 256>>>();
    // 7. output proj + gated residual
    mma_gemm<2,false><<<dim3(12, 16, 1), 256, MMSM>>>(p_attn, Wo, p_hs1,
        NTOK, DIMM, DIMM, 0, 0, 0, NFP, hidden, p_tg1, NIP, NFP, NIP);
    // 8. LN2
    ln_mod_kernel<<<NTOK, 256>>>(p_hs1, p_scale2, p_mod2, p_normed2);
    // 9. router
    tembdot_kernel<<<1, 1024>>>(temb, Wg);
    router_kernel<<<NTOK, 128>>>(Wg);
    topk_kernel<<<BSZ*NE, 512>>>();
    zero_sums_kernel<<<8, 256>>>();
    sum_acc_kernel<<<64, 256>>>();
    gate_norm_kernel<<<64, 256>>>();
    // 10. expert GEMM 1 (gathered A rows, batched over 16 experts)
    mma_gemm<0,true><<<dim3(21, 8, 16), 256, MMSM>>>(p_mod2, We_in, p_hmoe,
        BSZ*CAP, 2*NI, DIMM,
        0, (long long)2*NI*DIMM, (long long)BSZ*CAP*2*NI,
        NFP, NFP, NFP, NIP, NFP, p_rowmap);
    swiglu_kernel<<<MROWS, 256>>>(p_hmoe, p_actmoe);
    // 11. shared expert
    mma_gemm<0,false><<<dim3(21, 16, 1), 256, MMSM>>>(p_mod2, Ws_in, p_hsh,
        NTOK, 2*NI, DIMM, 0, 0, 0, NFP, NFP, NFP, NIP, NFP, NIP);
    swiglu_kernel<<<NTOK, 256>>>(p_hsh, p_actsh);
    mma_gemm<0,false><<<dim3(12, 16, 1), 256, MMSM>>>(p_actsh, Ws_out, p_outflat,
        NTOK, DIMM, NI, 0, 0, 0, NFP, NFP, NFP, NIP, NFP, NIP);
    // 12. expert GEMM 2 with atomic scatter onto shared output
    mma_gemm<3,false><<<dim3(12, 8, 16), 256, MMSM>>>(p_actmoe, We_out, p_outflat,
        BSZ*CAP, DIMM, NI,
        (long long)BSZ*CAP*NI, (long long)DIMM*NI, 0,
        NFP, NFP, NFP, p_rowmap, p_rscale, NIP);
    // 13. final gated residual
    final_kernel<<<NTOK, 256>>>(out);
}

// round 9
// speedup vs baseline: 1.1290x; 1.0856x over previous
#include <cuda_runtime.h>
#include <cuda_fp16.h>
#include <math.h>
#include <stdint.h>

#define BSZ 2
#define SEQ 1024
#define TXT 512
#define DIMM 1536
#define NH 12
#define HDD 128
#define NKV 4
#define JD 3584
#define NE 16
#define NI 1344
#define CAP 512
#define LTOT 1536      // SEQ + TXT
#define NTOK 2048      // BSZ*SEQ
#define MROWS 16384    // NE*BSZ*CAP
#define IKV 512        // NKV*HDD
#define REP 3          // NH/NKV
#define EPSL 1e-6f

// ------------------------- fp32 scratch -------------------------------------
__device__ float g_scale1[BSZ*DIMM];
__device__ float g_tg1[BSZ*DIMM];
__device__ float g_scale2[BSZ*DIMM];
__device__ float g_tg2[BSZ*DIMM];
__device__ float g_ctx[BSZ*TXT*DIMM];
__device__ float g_q[NTOK*DIMM];
__device__ float g_kimg[NTOK*IKV];
__device__ float g_vimg[NTOK*IKV];
__device__ float g_ktxt[BSZ*TXT*IKV];
__device__ float g_vtxt[BSZ*TXT*IKV];
__device__ float g_k[BSZ*NKV*LTOT*HDD];
__device__ float g_v[BSZ*NKV*LTOT*HDD];
__device__ float g_hs1[NTOK*DIMM];
__device__ float g_normed2[NTOK*DIMM];
__device__ float g_tembdot[BSZ*NE];
__device__ float g_aff[BSZ*NE*SEQ];
__device__ int   g_topidx[BSZ*NE*CAP];
__device__ float g_gating[BSZ*NE*CAP];
__device__ float g_sums[NTOK];
__device__ int   g_rowmap[MROWS];
__device__ float g_rscale[MROWS];
__device__ float g_hmoe[(size_t)MROWS*2*NI];
__device__ float g_hsh[NTOK*2*NI];
__device__ float g_outflat[NTOK*DIMM];

// ------------------------- half hi/lo planes --------------------------------
__device__ __half g_enc_h[BSZ*TXT*JD],      g_enc_l[BSZ*TXT*JD];
__device__ __half g_Wenc_h[DIMM*JD],        g_Wenc_l[DIMM*JD];
__device__ __half g_Wq_h[DIMM*DIMM],        g_Wq_l[DIMM*DIMM];
__device__ __half g_Wk_h[IKV*DIMM],         g_Wk_l[IKV*DIMM];
__device__ __half g_Wv_h[IKV*DIMM],         g_Wv_l[IKV*DIMM];
__device__ __half g_Wak_h[IKV*DIMM],        g_Wak_l[IKV*DIMM];
__device__ __half g_Wav_h[IKV*DIMM],        g_Wav_l[IKV*DIMM];
__device__ __half g_Wo_h[DIMM*DIMM],        g_Wo_l[DIMM*DIMM];
__device__ __half g_Wein_h[(size_t)NE*2*NI*DIMM], g_Wein_l[(size_t)NE*2*NI*DIMM];
__device__ __half g_Weout_h[(size_t)NE*DIMM*NI],  g_Weout_l[(size_t)NE*DIMM*NI];
__device__ __half g_Wsin_h[2*NI*DIMM],      g_Wsin_l[2*NI*DIMM];
__device__ __half g_Wsout_h[DIMM*NI],       g_Wsout_l[DIMM*NI];
__device__ __half g_ctx_h[BSZ*TXT*DIMM],    g_ctx_l[BSZ*TXT*DIMM];
__device__ __half g_img_h[NTOK*DIMM],       g_img_l[NTOK*DIMM];
__device__ __half g_attn_h[NTOK*DIMM],      g_attn_l[NTOK*DIMM];
__device__ __half g_mod2_h[NTOK*DIMM],      g_mod2_l[NTOK*DIMM];
__device__ __half g_actsh_h[NTOK*NI],       g_actsh_l[NTOK*NI];
__device__ __half g_actmoe_h[(size_t)MROWS*NI], g_actmoe_l[(size_t)MROWS*NI];

// ======================= helpers ============================================
__device__ __forceinline__ uint32_t s2u(const void* p) {
    uint32_t a;
    asm("{ .reg .u64 t; cvta.to.shared.u64 t, %1; cvt.u32.u64 %0, t; }"
        : "=r"(a) : "l"(p));
    return a;
}
__device__ __forceinline__ void cpa16(uint32_t d, const void* s) {
    asm volatile("cp.async.cg.shared.global [%0], [%1], 16;" :: "r"(d), "l"(s));
}
__device__ __forceinline__ void split2(float x, __half& h, __half& l) {
    h = __float2half(x);
    l = __float2half(x - __half2float(h));
}
__device__ __forceinline__ void mma16816(float* c, const uint32_t* a, const uint32_t* b) {
    asm volatile(
        "mma.sync.aligned.m16n8k16.row.col.f32.f16.f16.f32 "
        "{%0,%1,%2,%3}, {%4,%5,%6,%7}, {%8,%9}, {%0,%1,%2,%3};"
        : "+f"(c[0]), "+f"(c[1]), "+f"(c[2]), "+f"(c[3])
        : "r"(a[0]), "r"(a[1]), "r"(a[2]), "r"(a[3]), "r"(b[0]), "r"(b[1]));
}

// ------------------------- fp32 -> (hi,lo) half conversion -------------------
__global__ __launch_bounds__(256) void cvt_kernel(const float* __restrict__ src,
                                                  __half* __restrict__ dh,
                                                  __half* __restrict__ dl,
                                                  long long n) {
    long long i = ((long long)blockIdx.x * 256 + threadIdx.x) * 4;
    if (i >= n) return;
    float4 v = *(const float4*)(src + i);
    __half h0, h1, h2, h3, l0, l1, l2, l3;
    split2(v.x, h0, l0); split2(v.y, h1, l1);
    split2(v.z, h2, l2); split2(v.w, h3, l3);
    __half2* ph = (__half2*)(dh + i);
    ph[0] = __halves2half2(h0, h1); ph[1] = __halves2half2(h2, h3);
    __half2* pl = (__half2*)(dl + i);
    pl[0] = __halves2half2(l0, l1); pl[1] = __halves2half2(l2, l3);
}

// ======================= pipelined split-fp16 GEMM ==========================
// C[M,N] = A[M,K]*B[N,K]^T; inputs pre-split to (hi,lo) half planes.
//   acc += Ah*Bh + Ah*Bl + Al*Bh
// cp.async double-buffered smem (4 planes x 2 bufs x 10KB = 80KB), CTA tile
// 128x128, K-chunk 32, 8 warps (2x4), warp tile 64x32.
// EPI 0: store  1: +bias[n]  2: resid + gate[b][n]*acc  3: atomic scatter
// AG: gather A rows through agather[z*M + m].
#define PRS 80
#define PLSZ (128*PRS)          // 10240
#define BUFSZ (4*PLSZ)          // 40960
#define MMSM (2*BUFSZ)          // 81920

template<int EPI, bool AG>
__global__ __launch_bounds__(256, 2) void mma_gemm(
    const __half* __restrict__ Ah, const __half* __restrict__ Al,
    const __half* __restrict__ Bh, const __half* __restrict__ Bl,
    float* __restrict__ C,
    int M, int N, int K,
    long long sA, long long sB, long long sC,
    const float* __restrict__ bias,
    const float* __restrict__ resid, const float* __restrict__ gate,
    const int* __restrict__ rowmap, const float* __restrict__ rscale,
    const int* __restrict__ agather)
{
    extern __shared__ char smem[];
    const int tid = threadIdx.x;
    const int wid = tid >> 5, lane = tid & 31;
    const int z = blockIdx.z;
    const int m0 = blockIdx.y * 128, n0 = blockIdx.x * 128;
    if (!AG) { Ah += (long long)z * sA; Al += (long long)z * sA; }
    Bh += (long long)z * sB; Bl += (long long)z * sB;

    // ---- loader: thread owns row lr, 32B half-row lh ----
    const int lr = tid >> 1;
    const int lh = tid & 1;
    long long arow = AG ? (long long)agather[(long long)z * M + m0 + lr]
                        : (long long)(m0 + lr);
    const __half* aHp = Ah + arow * (long long)K + lh * 16;
    const __half* aLp = Al + arow * (long long)K + lh * 16;
    const __half* bHp = Bh + (long long)(n0 + lr) * K + lh * 16;
    const __half* bLp = Bl + (long long)(n0 + lr) * K + lh * 16;
    const uint32_t pofs = lr * PRS + lh * 32;

    const uint32_t uAh = s2u(smem);
    const uint32_t uAl = uAh + PLSZ;
    const uint32_t uBh = uAh + 2 * PLSZ;
    const uint32_t uBl = uAh + 3 * PLSZ;

    // ---- warp tile / ldmatrix offsets ----
    const int wm = (wid >> 2) * 64;
    const int wn = (wid & 3) * 32;
    uint32_t a_off[4];
    #pragma unroll
    for (int mt = 0; mt < 4; mt++) {
        int r = wm + mt * 16 + (lane & 15);
        a_off[mt] = r * PRS + (lane >> 4) * 16;
    }
    uint32_t b_off[2];
    #pragma unroll
    for (int np = 0; np < 2; np++) {
        int r = wn + np * 16 + ((lane >> 4) << 3) + (lane & 7);
        b_off[np] = r * PRS + ((lane >> 3) & 1) * 16;
    }

    float acc[4][4][4];
    #pragma unroll
    for (int mt = 0; mt < 4; mt++)
        #pragma unroll
        for (int nt = 0; nt < 4; nt++)
            #pragma unroll
            for (int i = 0; i < 4; i++) acc[mt][nt][i] = 0.f;

    const int NC = K >> 5;
    auto issue = [&](int c, uint32_t boff) {
        long long ko = (long long)c * 32;
        cpa16(uAh + boff + pofs,      aHp + ko);
        cpa16(uAh + boff + pofs + 16, aHp + ko + 8);
        cpa16(uAl + boff + pofs,      aLp + ko);
        cpa16(uAl + boff + pofs + 16, aLp + ko + 8);
        cpa16(uBh + boff + pofs,      bHp + ko);
        cpa16(uBh + boff + pofs + 16, bHp + ko + 8);
        cpa16(uBl + boff + pofs,      bLp + ko);
        cpa16(uBl + boff + pofs + 16, bLp + ko + 8);
        asm volatile("cp.async.commit_group;");
    };

    issue(0, 0);
    for (int c = 0; c < NC; c++) {
        const uint32_t boff = (c & 1) * BUFSZ;
        if (c + 1 < NC) {
            issue(c + 1, (~c & 1) * BUFSZ);
            asm volatile("cp.async.wait_group 1;");
        } else {
            asm volatile("cp.async.wait_group 0;");
        }
        __syncthreads();
        #pragma unroll
        for (int ks = 0; ks < 2; ks++) {
            uint32_t bh[4][2], bl[4][2];
            #pragma unroll
            for (int np = 0; np < 2; np++) {
                asm volatile("ldmatrix.sync.aligned.m8n8.x4.shared.b16 {%0,%1,%2,%3}, [%4];"
                    : "=r"(bh[np*2][0]), "=r"(bh[np*2][1]),
                      "=r"(bh[np*2+1][0]), "=r"(bh[np*2+1][1])
                    : "r"(uBh + boff + b_off[np] + ks * 32));
                asm volatile("ldmatrix.sync.aligned.m8n8.x4.shared.b16 {%0,%1,%2,%3}, [%4];"
                    : "=r"(bl[np*2][0]), "=r"(bl[np*2][1]),
                      "=r"(bl[np*2+1][0]), "=r"(bl[np*2+1][1])
                    : "r"(uBl + boff + b_off[np] + ks * 32));
            }
            #pragma unroll
            for (int mt = 0; mt < 4; mt++) {
                uint32_t ah[4], al[4];
                asm volatile("ldmatrix.sync.aligned.m8n8.x4.shared.b16 {%0,%1,%2,%3}, [%4];"
                    : "=r"(ah[0]), "=r"(ah[1]), "=r"(ah[2]), "=r"(ah[3])
                    : "r"(uAh + boff + a_off[mt] + ks * 32));
                asm volatile("ldmatrix.sync.aligned.m8n8.x4.shared.b16 {%0,%1,%2,%3}, [%4];"
                    : "=r"(al[0]), "=r"(al[1]), "=r"(al[2]), "=r"(al[3])
                    : "r"(uAl + boff + a_off[mt] + ks * 32));
                #pragma unroll
                for (int nt = 0; nt < 4; nt++) mma16816(acc[mt][nt], ah, bh[nt]);
                #pragma unroll
                for (int nt = 0; nt < 4; nt++) mma16816(acc[mt][nt], ah, bl[nt]);
                #pragma unroll
                for (int nt = 0; nt < 4; nt++) mma16816(acc[mt][nt], al, bh[nt]);
            }
        }
        __syncthreads();
    }

    // ---- epilogue ----
    const int g = lane >> 2;
    const int cp2 = (lane & 3) * 2;
    #pragma unroll
    for (int mt = 0; mt < 4; mt++) {
        #pragma unroll
        for (int hh = 0; hh < 2; hh++) {
            int row = m0 + wm + mt * 16 + g + hh * 8;
            if (EPI == 3) {
                long long gr = (long long)z * M + row;
                int trow = rowmap[gr];
                float s = rscale[gr];
                float* cp = C + (long long)trow * N;
                #pragma unroll
                for (int nt = 0; nt < 4; nt++) {
                    int col = n0 + wn + nt * 8 + cp2;
                    atomicAdd(cp + col,     acc[mt][nt][hh*2]   * s);
                    atomicAdd(cp + col + 1, acc[mt][nt][hh*2+1] * s);
                }
            } else {
                float* Cz = C + (long long)z * sC + (long long)row * N;
                #pragma unroll
                for (int nt = 0; nt < 4; nt++) {
                    int col = n0 + wn + nt * 8 + cp2;
                    float v0 = acc[mt][nt][hh*2], v1 = acc[mt][nt][hh*2+1];
                    if (EPI == 1) { v0 += bias[col]; v1 += bias[col + 1]; }
                    if (EPI == 2) {
                        const float* gp = gate + (row / SEQ) * N + col;
                        const float* rp = resid + (long long)row * N + col;
                        v0 = rp[0] + gp[0] * v0;
                        v1 = rp[1] + gp[1] * v1;
                    }
                    *(float2*)(Cz + col) = make_float2(v0, v1);
                }
            }
        }
    }
}

// ------------------------- modulation ----------------------------------------
__global__ __launch_bounds__(256) void mod_kernel(const float* __restrict__ temb,
                                                  const float* __restrict__ Wm,
                                                  const float* __restrict__ bm) {
    int gw = (blockIdx.x * blockDim.x + threadIdx.x) >> 5;
    int lane = threadIdx.x & 31;
    if (gw >= BSZ * 4 * DIMM) return;
    int b = gw / (4 * DIMM);
    int j = gw - b * 4 * DIMM;
    const float* t = temb + b * DIMM;
    const float* w = Wm + (size_t)j * DIMM;
    float acc = 0.f;
    for (int kk = lane; kk < DIMM; kk += 32) {
        float x = t[kk];
        acc += (x / (1.f + __expf(-x))) * w[kk];
    }
    #pragma unroll
    for (int o = 16; o; o >>= 1) acc += __shfl_xor_sync(0xffffffffu, acc, o);
    if (lane == 0) {
        acc += bm[j];
        int q = j / DIMM, c = j - q * DIMM;
        if (q == 0)      g_scale1[b*DIMM + c] = 1.f + acc;
        else if (q == 1) g_tg1[b*DIMM + c]    = tanhf(fminf(fmaxf(acc, -2.f), 2.f));
        else if (q == 2) g_scale2[b*DIMM + c] = 1.f + acc;
        else             g_tg2[b*DIMM + c]    = tanhf(fminf(fmaxf(acc, -2.f), 2.f));
    }
}

// ------------------------- LayerNorm -> half pairs (+opt fp32 normed) -------
__global__ __launch_bounds__(256) void ln_mod_kernel(const float* __restrict__ in,
                                                     const float* __restrict__ scale,
                                                     __half* __restrict__ mh,
                                                     __half* __restrict__ ml,
                                                     float* __restrict__ outnorm) {
    int rowi = blockIdx.x;
    int b = rowi >> 10;
    const float* x = in + (size_t)rowi * DIMM;
    float s = 0.f, sq = 0.f;
    for (int d = threadIdx.x; d < DIMM; d += 256) { float v = x[d]; s += v; sq += v * v; }
    #pragma unroll
    for (int o = 16; o; o >>= 1) {
        s  += __shfl_xor_sync(0xffffffffu, s,  o);
        sq += __shfl_xor_sync(0xffffffffu, sq, o);
    }
    __shared__ float rs[8], rq[8], mv[2];
    int w = threadIdx.x >> 5;
    if ((threadIdx.x & 31) == 0) { rs[w] = s; rq[w] = sq; }
    __syncthreads();
    if (threadIdx.x == 0) {
        float S = 0.f, Q = 0.f;
        for (int i = 0; i < 8; i++) { S += rs[i]; Q += rq[i]; }
        float mean = S / DIMM;
        float var = Q / DIMM - mean * mean;
        mv[0] = mean; mv[1] = rsqrtf(var + EPSL);
    }
    __syncthreads();
    float mean = mv[0], rstd = mv[1];
    const float* sc = scale + (size_t)b * DIMM;
    for (int d = threadIdx.x; d < DIMM; d += 256) {
        float n = (x[d] - mean) * rstd;
        if (outnorm) outnorm[(size_t)rowi * DIMM + d] = n;
        float m = n * sc[d];
        __half h, l; split2(m, h, l);
        mh[(size_t)rowi * DIMM + d] = h;
        ml[(size_t)rowi * DIMM + d] = l;
    }
}

// ------------------------- per-head RMSNorm of Q ----------------------------
__global__ __launch_bounds__(256) void rms_q_kernel(const float* __restrict__ w) {
    int gw = (blockIdx.x * blockDim.x + threadIdx.x) >> 5;
    if (gw >= NTOK * NH) return;
    int lane = threadIdx.x & 31;
    float* p = g_q + (size_t)gw * HDD;
    int d4 = lane << 2;
    float4 v = *(float4*)(p + d4);
    float ss = v.x*v.x + v.y*v.y + v.z*v.z + v.w*v.w;
    #pragma unroll
    for (int o = 16; o; o >>= 1) ss += __shfl_xor_sync(0xffffffffu, ss, o);
    float r = rsqrtf(ss / HDD + EPSL);
    float4 wv = *(const float4*)(w + d4);
    v.x *= r * wv.x; v.y *= r * wv.y; v.z *= r * wv.z; v.w *= r * wv.w;
    *(float4*)(p + d4) = v;
}

// ------------------------- K RMS + K/V repack -------------------------------
__global__ __launch_bounds__(256) void kv_repack_kernel(const float* __restrict__ nk,
                                                        const float* __restrict__ nak) {
    int gw = (blockIdx.x * blockDim.x + threadIdx.x) >> 5;
    if (gw >= BSZ * NKV * LTOT) return;
    int lane = threadIdx.x & 31;
    int l = gw % LTOT;
    int bk = gw / LTOT;
    int kv = bk % NKV, b = bk / NKV;
    const float *ksrc, *vsrc, *w;
    if (l < SEQ) {
        ksrc = g_kimg + (size_t)(b * SEQ + l) * IKV + kv * HDD;
        vsrc = g_vimg + (size_t)(b * SEQ + l) * IKV + kv * HDD;
        w = nk;
    } else {
        int tt = l - SEQ;
        ksrc = g_ktxt + (size_t)(b * TXT + tt) * IKV + kv * HDD;
        vsrc = g_vtxt + (size_t)(b * TXT + tt) * IKV + kv * HDD;
        w = nak;
    }
    int d4 = lane << 2;
    float4 kvv = *(const float4*)(ksrc + d4);
    float ss = kvv.x*kvv.x + kvv.y*kvv.y + kvv.z*kvv.z + kvv.w*kvv.w;
    #pragma unroll
    for (int o = 16; o; o >>= 1) ss += __shfl_xor_sync(0xffffffffu, ss, o);
    float r = rsqrtf(ss / HDD + EPSL);
    float4 wv = *(const float4*)(w + d4);
    kvv.x *= r * wv.x; kvv.y *= r * wv.y; kvv.z *= r * wv.z; kvv.w *= r * wv.w;
    size_t dst = ((size_t)(b * NKV + kv) * LTOT + l) * HDD + d4;
    *(float4*)(g_k + dst) = kvv;
    *(float4*)(g_v + dst) = *(const float4*)(vsrc + d4);
}

// ------------------------- flash attention -> half pairs --------------------
__global__ __launch_bounds__(256) void flash_kernel() {
    __shared__ float Qs[32][129];
    __shared__ float KVs[32][129];
    __shared__ float Ss[32][33];
    const int q0 = blockIdx.x * 32;
    const int h = blockIdx.y;
    const int b = blockIdx.z;
    const int kv = h / REP;
    const int t = threadIdx.x;
    for (int idx = t; idx < 1024; idx += 256) {
        int qi = idx >> 5, d4 = (idx & 31) << 2;
        float4 v = *(const float4*)(g_q + (size_t)(b * SEQ + q0 + qi) * DIMM + h * HDD + d4);
        Qs[qi][d4] = v.x; Qs[qi][d4+1] = v.y; Qs[qi][d4+2] = v.z; Qs[qi][d4+3] = v.w;
    }
    const int q = t >> 3, dg = t & 7;
    float acc[16];
    #pragma unroll
    for (int i = 0; i < 16; i++) acc[i] = 0.f;
    float m = -1e30f, l = 0.f;
    const float sc = 0.08838834764831845f;  // 1/sqrt(128)
    const float* kbase = g_k + (size_t)(b * NKV + kv) * LTOT * HDD;
    const float* vbase = g_v + (size_t)(b * NKV + kv) * LTOT * HDD;
    __syncthreads();
    for (int k0 = 0; k0 < LTOT; k0 += 32) {
        for (int idx = t; idx < 1024; idx += 256) {
            int ki = idx >> 5, d4 = (idx & 31) << 2;
            float4 v = *(const float4*)(kbase + (size_t)(k0 + ki) * HDD + d4);
            KVs[ki][d4] = v.x; KVs[ki][d4+1] = v.y; KVs[ki][d4+2] = v.z; KVs[ki][d4+3] = v.w;
        }
        __syncthreads();
        {
            int kb = dg << 2;
            float s0 = 0.f, s1 = 0.f, s2 = 0.f, s3 = 0.f;
            #pragma unroll 4
            for (int d = 0; d < 128; d++) {
                float qv = Qs[q][d];
                s0 += qv * KVs[kb][d];
                s1 += qv * KVs[kb+1][d];
                s2 += qv * KVs[kb+2][d];
                s3 += qv * KVs[kb+3][d];
            }
            Ss[q][kb] = s0 * sc; Ss[q][kb+1] = s1 * sc;
            Ss[q][kb+2] = s2 * sc; Ss[q][kb+3] = s3 * sc;
        }
        __syncthreads();
        float srow[32];
        float rmax = -1e30f;
        #pragma unroll
        for (int k = 0; k < 32; k++) { srow[k] = Ss[q][k]; rmax = fmaxf(rmax, srow[k]); }
        for (int idx = t; idx < 1024; idx += 256) {
            int ki = idx >> 5, d4 = (idx & 31) << 2;
            float4 v = *(const float4*)(vbase + (size_t)(k0 + ki) * HDD + d4);
            KVs[ki][d4] = v.x; KVs[ki][d4+1] = v.y; KVs[ki][d4+2] = v.z; KVs[ki][d4+3] = v.w;
        }
        float newm = fmaxf(m, rmax);
        float corr = __expf(m - newm);
        float psum = 0.f;
        #pragma unroll
        for (int k = 0; k < 32; k++) { srow[k] = __expf(srow[k] - newm); psum += srow[k]; }
        l = l * corr + psum;
        m = newm;
        #pragma unroll
        for (int i = 0; i < 16; i++) acc[i] *= corr;
        __syncthreads();
        #pragma unroll
        for (int k = 0; k < 32; k++) {
            float p = srow[k];
            #pragma unroll
            for (int i = 0; i < 16; i++) acc[i] += p * KVs[k][dg + (i << 3)];
        }
        __syncthreads();
    }
    float inv = 1.f / l;
    size_t obase = (size_t)(b * SEQ + q0 + q) * DIMM + h * HDD;
    #pragma unroll
    for (int i = 0; i < 16; i++) {
        float v = acc[i] * inv;
        __half hh, ll; split2(v, hh, ll);
        g_attn_h[obase + dg + (i << 3)] = hh;
        g_attn_l[obase + dg + (i << 3)] = ll;
    }
}

// ------------------------- router ------------------------------------------
__global__ __launch_bounds__(1024) void tembdot_kernel(const float* __restrict__ temb,
                                                       const float* __restrict__ Wg) {
    int wid = threadIdx.x >> 5, lane = threadIdx.x & 31;
    int b = wid / NE, e = wid % NE;
    const float* t = temb + b * DIMM;
    const float* w = Wg + (size_t)e * 2 * DIMM;
    float acc = 0.f;
    for (int d = lane; d < DIMM; d += 32) acc += t[d] * w[d];
    #pragma unroll
    for (int o = 16; o; o >>= 1) acc += __shfl_xor_sync(0xffffffffu, acc, o);
    if (lane == 0) g_tembdot[wid] = acc;
}

__global__ __launch_bounds__(128) void router_kernel(const float* __restrict__ Wg) {
    __shared__ float lg[NE];
    int tokid = blockIdx.x;
    int b = tokid >> 10, s = tokid & 1023;
    int w = threadIdx.x >> 5, lane = threadIdx.x & 31;
    const float* x = g_normed2 + (size_t)tokid * DIMM;
    for (int e = w * 4; e < w * 4 + 4; e++) {
        const float* wg = Wg + (size_t)e * 2 * DIMM + DIMM;
        float acc = 0.f;
        for (int d = lane; d < DIMM; d += 32) acc += x[d] * wg[d];
        #pragma unroll
        for (int o = 16; o; o >>= 1) acc += __shfl_xor_sync(0xffffffffu, acc, o);
        if (lane == 0) lg[e] = acc + g_tembdot[b * NE + e];
    }
    __syncthreads();
    if (threadIdx.x == 0) {
        float mx = -1e30f;
        for (int e = 0; e < NE; e++) mx = fmaxf(mx, lg[e]);
        float ex[NE], sm = 0.f;
        for (int e = 0; e < NE; e++) { ex[e] = __expf(lg[e] - mx); sm += ex[e]; }
        float inv = 1.f / sm;
        for (int e = 0; e < NE; e++)
            g_aff[((size_t)(b * NE + e)) * SEQ + s] = ex[e] * inv;
    }
}

// ------------------------- exact top-k via bitonic sort ---------------------
__global__ __launch_bounds__(512) void topk_kernel() {
    __shared__ float v[1024];
    __shared__ int   id[1024];
    int be = blockIdx.x;
    const float* rowp = g_aff + (size_t)be * SEQ;
    int t = threadIdx.x;
    for (int i = t; i < 1024; i += 512) { v[i] = rowp[i]; id[i] = i; }
    __syncthreads();
    for (int k = 2; k <= 1024; k <<= 1) {
        for (int j = k >> 1; j > 0; j >>= 1) {
            for (int i = t; i < 1024; i += 512) {
                int ixj = i ^ j;
                if (ixj > i) {
                    bool up = ((i & k) == 0);
                    float va = v[i], vb = v[ixj];
                    int ia = id[i], ib = id[ixj];
                    bool a_first = (va > vb) || (va == vb && ia < ib);
                    bool sw = up ? !a_first : a_first;
                    if (sw) { v[i] = vb; v[ixj] = va; id[i] = ib; id[ixj] = ia; }
                }
            }
            __syncthreads();
        }
    }
    if (t < CAP) {
        g_gating[be * CAP + t] = v[t];
        g_topidx[be * CAP + t] = id[t];
    }
}

__global__ void zero_sums_kernel() {
    int i = blockIdx.x * blockDim.x + threadIdx.x;
    if (i < NTOK) g_sums[i] = 0.f;
}

__global__ void sum_acc_kernel() {
    int i = blockIdx.x * blockDim.x + threadIdx.x;
    if (i >= BSZ * NE * CAP) return;
    int be = i / CAP;
    int b = be / NE;
    int tok = b * SEQ + g_topidx[i];
    atomicAdd(&g_sums[tok], g_gating[i]);
}

__global__ void gate_norm_kernel() {
    int i = blockIdx.x * blockDim.x + threadIdx.x;
    if (i >= BSZ * NE * CAP) return;
    int c = i % CAP;
    int be = i / CAP;
    int b = be / NE, e = be % NE;
    int tok = b * SEQ + g_topidx[i];
    float g = g_gating[i] / (g_sums[tok] + 1e-12f) * 2.5f;
    int rowflat = (e * BSZ + b) * CAP + c;
    g_rowmap[rowflat] = tok;
    g_rscale[rowflat] = g;
}

// ------------------------- swiglu -> half pairs ------------------------------
__global__ __launch_bounds__(256) void swiglu_kernel(const float* __restrict__ h,
                                                     __half* __restrict__ oh,
                                                     __half* __restrict__ ol) {
    int r = blockIdx.x;
    const float4* a = (const float4*)(h + (size_t)r * 2 * NI);
    const float4* g = (const float4*)(h + (size_t)r * 2 * NI + NI);
    for (int i = threadIdx.x; i < NI / 4; i += 256) {
        float4 av = a[i], gv = g[i];
        float f0 = av.x * (gv.x / (1.f + __expf(-gv.x)));
        float f1 = av.y * (gv.y / (1.f + __expf(-gv.y)));
        float f2 = av.z * (gv.z / (1.f + __expf(-gv.z)));
        float f3 = av.w * (gv.w / (1.f + __expf(-gv.w)));
        __half h0, h1, h2, h3, l0, l1, l2, l3;
        split2(f0, h0, l0); split2(f1, h1, l1);
        split2(f2, h2, l2); split2(f3, h3, l3);
        __half2* ph = (__half2*)(oh + (size_t)r * NI + i * 4);
        ph[0] = __halves2half2(h0, h1); ph[1] = __halves2half2(h2, h3);
        __half2* pl = (__half2*)(ol + (size_t)r * NI + i * 4);
        pl[0] = __halves2half2(l0, l1); pl[1] = __halves2half2(l2, l3);
    }
}

// ------------------------- final residual -----------------------------------
__global__ __launch_bounds__(256) void final_kernel(float* __restrict__ out) {
    int r = blockIdx.x;
    int b = r >> 10;
    const float4* hs = (const float4*)(g_hs1 + (size_t)r * DIMM);
    const float4* mo = (const float4*)(g_outflat + (size_t)r * DIMM);
    const float4* gg = (const float4*)(g_tg2 + (size_t)b * DIMM);
    float4* o = (float4*)(out + (size_t)r * DIMM);
    for (int i = threadIdx.x; i < DIMM / 4; i += 256) {
        float4 h = hs[i], m = mo[i], g = gg[i], v;
        v.x = h.x + g.x * m.x; v.y = h.y + g.y * m.y;
        v.z = h.z + g.z * m.z; v.w = h.w + g.w * m.w;
        o[i] = v;
    }
}

// ------------------------- launcher -----------------------------------------
extern "C" void kernel_launch(void* const* d_in, const int* in_sizes, int n_in,
                              void* d_out, int out_size) {
    const float* hidden = (const float*)d_in[0];
    const float* enc    = (const float*)d_in[1];
    const float* temb   = (const float*)d_in[2];
    const float* W_mod  = (const float*)d_in[3];
    const float* b_mod  = (const float*)d_in[4];
    const float* W_enc  = (const float*)d_in[5];
    const float* b_enc  = (const float*)d_in[6];
    const float* Wq     = (const float*)d_in[7];
    const float* Wk     = (const float*)d_in[8];
    const float* Wv     = (const float*)d_in[9];
    const float* Wak    = (const float*)d_in[10];
    const float* Wav    = (const float*)d_in[11];
    const float* nq_w   = (const float*)d_in[12];
    const float* nk_w   = (const float*)d_in[13];
    const float* nak_w  = (const float*)d_in[14];
    const float* Wo     = (const float*)d_in[15];
    const float* Wg     = (const float*)d_in[16];
    const float* We_in  = (const float*)d_in[17];
    const float* We_out = (const float*)d_in[18];
    const float* Ws_in  = (const float*)d_in[19];
    const float* Ws_out = (const float*)d_in[20];
    float* out = (float*)d_out;

    void* pv;
    #define GF(sym) (cudaGetSymbolAddress(&pv, sym), (float*)pv)
    #define GH(sym) (cudaGetSymbolAddress(&pv, sym), (__half*)pv)
    #define GI(sym) (cudaGetSymbolAddress(&pv, sym), (int*)pv)
    float* p_ctx     = GF(g_ctx);
    float* p_q       = GF(g_q);
    float* p_kimg    = GF(g_kimg);
    float* p_vimg    = GF(g_vimg);
    float* p_ktxt    = GF(g_ktxt);
    float* p_vtxt    = GF(g_vtxt);
    float* p_hs1     = GF(g_hs1);
    float* p_normed2 = GF(g_normed2);
    float* p_hmoe    = GF(g_hmoe);
    float* p_hsh     = GF(g_hsh);
    float* p_outflat = GF(g_outflat);
    float* p_scale1  = GF(g_scale1);
    float* p_scale2  = GF(g_scale2);
    float* p_tg1     = GF(g_tg1);
    int*   p_rowmap  = GI(g_rowmap);
    float* p_rscale  = GF(g_rscale);
    __half *p_enc_h = GH(g_enc_h),   *p_enc_l = GH(g_enc_l);
    __half *p_Wenc_h = GH(g_Wenc_h), *p_Wenc_l = GH(g_Wenc_l);
    __half *p_Wq_h = GH(g_Wq_h),     *p_Wq_l = GH(g_Wq_l);
    __half *p_Wk_h = GH(g_Wk_h),     *p_Wk_l = GH(g_Wk_l);
    __half *p_Wv_h = GH(g_Wv_h),     *p_Wv_l = GH(g_Wv_l);
    __half *p_Wak_h = GH(g_Wak_h),   *p_Wak_l = GH(g_Wak_l);
    __half *p_Wav_h = GH(g_Wav_h),   *p_Wav_l = GH(g_Wav_l);
    __half *p_Wo_h = GH(g_Wo_h),     *p_Wo_l = GH(g_Wo_l);
    __half *p_Wein_h = GH(g_Wein_h), *p_Wein_l = GH(g_Wein_l);
    __half *p_Weout_h = GH(g_Weout_h), *p_Weout_l = GH(g_Weout_l);
    __half *p_Wsin_h = GH(g_Wsin_h), *p_Wsin_l = GH(g_Wsin_l);
    __half *p_Wsout_h = GH(g_Wsout_h), *p_Wsout_l = GH(g_Wsout_l);
    __half *p_ctx_h = GH(g_ctx_h),   *p_ctx_l = GH(g_ctx_l);
    __half *p_img_h = GH(g_img_h),   *p_img_l = GH(g_img_l);
    __half *p_attn_h = GH(g_attn_h), *p_attn_l = GH(g_attn_l);
    __half *p_mod2_h = GH(g_mod2_h), *p_mod2_l = GH(g_mod2_l);
    __half *p_actsh_h = GH(g_actsh_h), *p_actsh_l = GH(g_actsh_l);
    __half *p_actmoe_h = GH(g_actmoe_h), *p_actmoe_l = GH(g_actmoe_l);

    cudaFuncSetAttribute(mma_gemm<0,false>, cudaFuncAttributeMaxDynamicSharedMemorySize, MMSM);
    cudaFuncSetAttribute(mma_gemm<1,false>, cudaFuncAttributeMaxDynamicSharedMemorySize, MMSM);
    cudaFuncSetAttribute(mma_gemm<2,false>, cudaFuncAttributeMaxDynamicSharedMemorySize, MMSM);
    cudaFuncSetAttribute(mma_gemm<3,false>, cudaFuncAttributeMaxDynamicSharedMemorySize, MMSM);
    cudaFuncSetAttribute(mma_gemm<0,true>,  cudaFuncAttributeMaxDynamicSharedMemorySize, MMSM);

    const float* NFP = nullptr;
    const int*   NIP = nullptr;

    #define CVT(src, dh, dl, n) \
        cvt_kernel<<<(int)(((n)/4 + 255)/256), 256>>>(src, dh, dl, (long long)(n))

    // 0. convert weights + enc to half pairs
    CVT(W_enc, p_Wenc_h, p_Wenc_l, (long long)DIMM*JD);
    CVT(Wq,  p_Wq_h,  p_Wq_l,  (long long)DIMM*DIMM);
    CVT(Wk,  p_Wk_h,  p_Wk_l,  (long long)IKV*DIMM);
    CVT(Wv,  p_Wv_h,  p_Wv_l,  (long long)IKV*DIMM);
    CVT(Wak, p_Wak_h, p_Wak_l, (long long)IKV*DIMM);
    CVT(Wav, p_Wav_h, p_Wav_l, (long long)IKV*DIMM);
    CVT(Wo,  p_Wo_h,  p_Wo_l,  (long long)DIMM*DIMM);
    CVT(We_in,  p_Wein_h,  p_Wein_l,  (long long)NE*2*NI*DIMM);
    CVT(We_out, p_Weout_h, p_Weout_l, (long long)NE*DIMM*NI);
    CVT(Ws_in,  p_Wsin_h,  p_Wsin_l,  (long long)2*NI*DIMM);
    CVT(Ws_out, p_Wsout_h, p_Wsout_l, (long long)DIMM*NI);
    CVT(enc, p_enc_h, p_enc_l, (long long)BSZ*TXT*JD);

    // 1. modulation
    mod_kernel<<<1536, 256>>>(temb, W_mod, b_mod);
    // 2. context projection (+bias), then convert ctx
    mma_gemm<1,false><<<dim3(12, 8, 1), 256, MMSM>>>(p_enc_h, p_enc_l,
        p_Wenc_h, p_Wenc_l, p_ctx, BSZ*TXT, DIMM, JD, 0, 0, 0,
        b_enc, NFP, NFP, NIP, NFP, NIP);
    CVT(p_ctx, p_ctx_h, p_ctx_l, (long long)BSZ*TXT*DIMM);
    // 3. LN1 * scale1 -> half pairs
    ln_mod_kernel<<<NTOK, 256>>>(hidden, p_scale1, p_img_h, p_img_l, nullptr);
    // 4. projections
    mma_gemm<0,false><<<dim3(12, 16, 1), 256, MMSM>>>(p_img_h, p_img_l,
        p_Wq_h, p_Wq_l, p_q, NTOK, DIMM, DIMM, 0, 0, 0, NFP, NFP, NFP, NIP, NFP, NIP);
    mma_gemm<0,false><<<dim3(4, 16, 1), 256, MMSM>>>(p_img_h, p_img_l,
        p_Wk_h, p_Wk_l, p_kimg, NTOK, IKV, DIMM, 0, 0, 0, NFP, NFP, NFP, NIP, NFP, NIP);
    mma_gemm<0,false><<<dim3(4, 16, 1), 256, MMSM>>>(p_img_h, p_img_l,
        p_Wv_h, p_Wv_l, p_vimg, NTOK, IKV, DIMM, 0, 0, 0, NFP, NFP, NFP, NIP, NFP, NIP);
    mma_gemm<0,false><<<dim3(4, 8, 1), 256, MMSM>>>(p_ctx_h, p_ctx_l,
        p_Wak_h, p_Wak_l, p_ktxt, BSZ*TXT, IKV, DIMM, 0, 0, 0, NFP, NFP, NFP, NIP, NFP, NIP);
    mma_gemm<0,false><<<dim3(4, 8, 1), 256, MMSM>>>(p_ctx_h, p_ctx_l,
        p_Wav_h, p_Wav_l, p_vtxt, BSZ*TXT, IKV, DIMM, 0, 0, 0, NFP, NFP, NFP, NIP, NFP, NIP);
    // 5. norms + repack
    rms_q_kernel<<<3072, 256>>>(nq_w);
    kv_repack_kernel<<<1536, 256>>>(nk_w, nak_w);
    // 6. attention (-> half pairs)
    flash_kernel<<<dim3(SEQ/32, NH, BSZ), 256>>>();
    // 7. output proj + gated residual
    mma_gemm<2,false><<<dim3(12, 16, 1), 256, MMSM>>>(p_attn_h, p_attn_l,
        p_Wo_h, p_Wo_l, p_hs1, NTOK, DIMM, DIMM, 0, 0, 0,
        NFP, hidden, p_tg1, NIP, NFP, NIP);
    // 8. LN2 -> mod2 half pairs + normed2 fp32
    ln_mod_kernel<<<NTOK, 256>>>(p_hs1, p_scale2, p_mod2_h, p_mod2_l, p_normed2);
    // 9. router
    tembdot_kernel<<<1, 1024>>>(temb, Wg);
    router_kernel<<<NTOK, 128>>>(Wg);
    topk_kernel<<<BSZ*NE, 512>>>();
    zero_sums_kernel<<<8, 256>>>();
    sum_acc_kernel<<<64, 256>>>();
    gate_norm_kernel<<<64, 256>>>();
    // 10. expert GEMM 1 (gathered A rows, batched over 16 experts)
    mma_gemm<0,true><<<dim3(21, 8, 16), 256, MMSM>>>(p_mod2_h, p_mod2_l,
        p_Wein_h, p_Wein_l, p_hmoe, BSZ*CAP, 2*NI, DIMM,
        0, (long long)2*NI*DIMM, (long long)BSZ*CAP*2*NI,
        NFP, NFP, NFP, NIP, NFP, p_rowmap);
    swiglu_kernel<<<MROWS, 256>>>(p_hmoe, p_actmoe_h, p_actmoe_l);
    // 11. shared expert
    mma_gemm<0,false><<<dim3(21, 16, 1), 256, MMSM>>>(p_mod2_h, p_mod2_l,
        p_Wsin_h, p_Wsin_l, p_hsh, NTOK, 2*NI, DIMM, 0, 0, 0,
        NFP, NFP, NFP, NIP, NFP, NIP);
    swiglu_kernel<<<NTOK, 256>>>(p_hsh, p_actsh_h, p_actsh_l);
    mma_gemm<0,false><<<dim3(12, 16, 1), 256, MMSM>>>(p_actsh_h, p_actsh_l,
        p_Wsout_h, p_Wsout_l, p_outflat, NTOK, DIMM, NI, 0, 0, 0,
        NFP, NFP, NFP, NIP, NFP, NIP);
    // 12. expert GEMM 2 with atomic scatter onto shared output
    mma_gemm<3,false><<<dim3(12, 8, 16), 256, MMSM>>>(p_actmoe_h, p_actmoe_l,
        p_Weout_h, p_Weout_l, p_outflat, BSZ*CAP, DIMM, NI,
        (long long)BSZ*CAP*NI, (long long)DIMM*NI, 0,
        NFP, NFP, NFP, p_rowmap, p_rscale, NIP);
    // 13. final gated residual
    final_kernel<<<NTOK, 256>>>(out);
}